// round 11
// baseline (speedup 1.0000x reference)
#include <cuda_runtime.h>
#include <cstdint>

typedef unsigned long long u64;

#define BB 512
#define SS 512
#define FF 64
#define HH 128
#define GG 512   // 4*H
#define OO 64

// ---- scratch (static __device__ globals: allocation-free rule) ----
__device__ float g_xp[(size_t)BB * SS * GG];   // 512 MB, reused across layers
__device__ float g_h0[(size_t)BB * SS * HH];   // 64 MB  (layer0 hidden sequence)
__device__ float g_h1[BB * HH];                // layer1 last hidden

// ---- packed f32x2 helpers (sm_103a FFMA2 path) ----
__device__ __forceinline__ u64 ffma2(u64 a, u64 b, u64 c) {
    u64 d; asm("fma.rn.f32x2 %0,%1,%2,%3;" : "=l"(d) : "l"(a), "l"(b), "l"(c)); return d;
}
__device__ __forceinline__ u64 pack2(float x) {
    u64 d; asm("mov.b64 %0,{%1,%1};" : "=l"(d) : "f"(x)); return d;
}
__device__ __forceinline__ float2 unpack2(u64 v) {
    float2 r; asm("mov.b64 {%0,%1},%2;" : "=f"(r.x), "=f"(r.y) : "l"(v)); return r;
}

__device__ __forceinline__ float sigf(float x) {
    return __fdividef(1.0f, 1.0f + __expf(-x));
}
__device__ __forceinline__ float tanhf_fast(float x) {
    return 1.0f - __fdividef(2.0f, __expf(2.0f * x) + 1.0f);
}

// =====================================================================
// Projection GEMM (FFMA2, double-buffered 16-k chunks, 2 CTAs/SM,
// W stored in SMEM as pre-duplicated u64 {w,w} — zero in-loop pack2):
// out[M,512] = A[M,K] @ W[512,K]^T + ba + bb
// grid = (M/128, 4), block = 256 (thread = 8m x 8n).
// =====================================================================
#define KPAD 136
#define TBUF (16 * KPAD)    // 2176 floats per A buffer
#define TBUFW (16 * KPAD)   // 2176 u64 per W buffer

template <int K>
__global__ __launch_bounds__(256, 2) void proj_kernel(
    const float* __restrict__ A, const float* __restrict__ W,
    const float* __restrict__ ba, const float* __restrict__ bb,
    float* __restrict__ out)
{
    extern __shared__ float sm[];
    float* smA = sm;                       // 2 x TBUF floats
    u64*   smW = (u64*)(sm + 2 * TBUF);    // 2 x TBUFW u64 (pre-duplicated)

    const int tid = threadIdx.x;
    const int m0 = blockIdx.x * 128;
    const int n0 = blockIdx.y * 128;
    const int NC = K / 16;

    const int rl = tid >> 2;       // load row 0..63
    const int k4 = tid & 3;        // k-quad within chunk

    {
        float4 a0 = *(const float4*)(A + (size_t)(m0 + rl) * K + k4 * 4);
        float4 a1 = *(const float4*)(A + (size_t)(m0 + rl + 64) * K + k4 * 4);
        float4 w0 = *(const float4*)(W + (size_t)(n0 + rl) * K + k4 * 4);
        float4 w1 = *(const float4*)(W + (size_t)(n0 + rl + 64) * K + k4 * 4);
        #pragma unroll
        for (int j = 0; j < 4; j++) {
            float av0 = (j==0)?a0.x:(j==1)?a0.y:(j==2)?a0.z:a0.w;
            float av1 = (j==0)?a1.x:(j==1)?a1.y:(j==2)?a1.z:a1.w;
            float wv0 = (j==0)?w0.x:(j==1)?w0.y:(j==2)?w0.z:w0.w;
            float wv1 = (j==0)?w1.x:(j==1)?w1.y:(j==2)?w1.z:w1.w;
            smA[(k4*4+j)*KPAD + rl]      = av0;
            smA[(k4*4+j)*KPAD + rl + 64] = av1;
            smW[(k4*4+j)*KPAD + rl]      = pack2(wv0);
            smW[(k4*4+j)*KPAD + rl + 64] = pack2(wv1);
        }
    }
    __syncthreads();

    const int mb = (tid >> 4) * 8;   // m-octet
    const int nb = (tid & 15) * 8;   // n-octet

    u64 acc[4][8];
    #pragma unroll
    for (int p = 0; p < 4; p++)
        #pragma unroll
        for (int j = 0; j < 8; j++) acc[p][j] = 0ull;

    int buf = 0;
    for (int c = 0; c < NC; c++) {
        float4 pa0, pa1, pw0, pw1;
        const bool pf = (c + 1 < NC);
        if (pf) {
            const int k0 = (c + 1) * 16;
            pa0 = *(const float4*)(A + (size_t)(m0 + rl) * K + k0 + k4 * 4);
            pa1 = *(const float4*)(A + (size_t)(m0 + rl + 64) * K + k0 + k4 * 4);
            pw0 = *(const float4*)(W + (size_t)(n0 + rl) * K + k0 + k4 * 4);
            pw1 = *(const float4*)(W + (size_t)(n0 + rl + 64) * K + k0 + k4 * 4);
        }

        const float* bA = smA + buf * TBUF;
        const u64*   bW = smW + buf * TBUFW;
        #pragma unroll
        for (int kk = 0; kk < 16; kk++) {
            ulonglong2 aA = *(const ulonglong2*)(bA + kk * KPAD + mb);
            ulonglong2 aB = *(const ulonglong2*)(bA + kk * KPAD + mb + 4);
            const u64* wrow = bW + kk * KPAD + nb;
            ulonglong2 w01 = ((const ulonglong2*)wrow)[0];
            ulonglong2 w23 = ((const ulonglong2*)wrow)[1];
            ulonglong2 w45 = ((const ulonglong2*)wrow)[2];
            ulonglong2 w67 = ((const ulonglong2*)wrow)[3];
            u64 ap[4] = {aA.x, aA.y, aB.x, aB.y};
            u64 wv[8] = {w01.x, w01.y, w23.x, w23.y, w45.x, w45.y, w67.x, w67.y};
            #pragma unroll
            for (int j = 0; j < 8; j++) {
                #pragma unroll
                for (int p = 0; p < 4; p++)
                    acc[p][j] = ffma2(ap[p], wv[j], acc[p][j]);
            }
        }

        if (pf) {
            float* dA = smA + (buf ^ 1) * TBUF;
            u64*   dW = smW + (buf ^ 1) * TBUFW;
            #pragma unroll
            for (int j = 0; j < 4; j++) {
                float av0 = (j==0)?pa0.x:(j==1)?pa0.y:(j==2)?pa0.z:pa0.w;
                float av1 = (j==0)?pa1.x:(j==1)?pa1.y:(j==2)?pa1.z:pa1.w;
                float wv0 = (j==0)?pw0.x:(j==1)?pw0.y:(j==2)?pw0.z:pw0.w;
                float wv1 = (j==0)?pw1.x:(j==1)?pw1.y:(j==2)?pw1.z:pw1.w;
                dA[(k4*4+j)*KPAD + rl]      = av0;
                dA[(k4*4+j)*KPAD + rl + 64] = av1;
                dW[(k4*4+j)*KPAD + rl]      = pack2(wv0);
                dW[(k4*4+j)*KPAD + rl + 64] = pack2(wv1);
            }
        }
        __syncthreads();
        buf ^= 1;
    }

    float bias[8];
    #pragma unroll
    for (int j = 0; j < 8; j++)
        bias[j] = ba[n0 + nb + j] + bb[n0 + nb + j];

    #pragma unroll
    for (int p = 0; p < 4; p++) {
        float r0[8], r1[8];
        #pragma unroll
        for (int j = 0; j < 8; j++) {
            float2 v = unpack2(acc[p][j]);
            r0[j] = v.x + bias[j];
            r1[j] = v.y + bias[j];
        }
        float* o0 = out + (size_t)(m0 + mb + 2 * p) * GG + n0 + nb;
        float* o1 = o0 + GG;
        *(float4*)(o0)     = make_float4(r0[0], r0[1], r0[2], r0[3]);
        *(float4*)(o0 + 4) = make_float4(r0[4], r0[5], r0[6], r0[7]);
        *(float4*)(o1)     = make_float4(r1[0], r1[1], r1[2], r1[3]);
        *(float4*)(o1 + 4) = make_float4(r1[4], r1[5], r1[6], r1[7]);
    }
}

// =====================================================================
// Recurrent LSTM layer (R9, unchanged — best measured: 1.285 ms/layer).
// split-k GEMM around the cluster barrier; cluster = 2 CTAs, 8 batch
// rows; CTA owns 64 hidden cols (256 gate rows). Thread = 2 rows x
// (16 own k + 16 peer k), 64 W regs. gsm coalesced. 128 CTAs x 512.
// =====================================================================
__global__ void __cluster_dims__(2, 1, 1) __launch_bounds__(512, 1) lstm_kernel(
    const float* __restrict__ xp,    // [B, S, 4H]
    const float* __restrict__ W_hh,  // [4H, H]
    float* __restrict__ hseq,        // [B, S, H]  (layer 0)
    float* __restrict__ hlast,       // [B, H]     (layer 1)
    int store_seq)
{
    extern __shared__ float sm[];
    float* hsm = sm;          // 2 x [2 grp][128 k][4 b] = 2 x 1024
    float* gsm = sm + 2048;   // [4 kq][8 b][256 row] = 8192

    const int tid    = threadIdx.x;
    const int rank   = blockIdx.x & 1;
    const int peer   = rank ^ 1;
    const int batch0 = (blockIdx.x >> 1) * 8;

    const int kq = tid >> 7;         // k-segment 0..3 (16 k within each half)
    const int rr = tid & 127;        // local row-pair id
    const int grow0 = (rr >> 6) * 128 + rank * 64 + (rr & 63);
    const int grow1 = grow0 + 256;

    const int ok = rank * 64 + kq * 16;   // own-half k base
    const int pk = peer * 64 + kq * 16;   // peer-half k base

    // ---- W into registers: [0..15] own-half k, [16..31] peer-half k
    float w0[32], w1[32];
    {
        const float4* q;
        q = (const float4*)(W_hh + (size_t)grow0 * HH + ok);
        #pragma unroll
        for (int j = 0; j < 4; j++) {
            float4 v = q[j];
            w0[4*j+0]=v.x; w0[4*j+1]=v.y; w0[4*j+2]=v.z; w0[4*j+3]=v.w;
        }
        q = (const float4*)(W_hh + (size_t)grow0 * HH + pk);
        #pragma unroll
        for (int j = 0; j < 4; j++) {
            float4 v = q[j];
            w0[16+4*j+0]=v.x; w0[16+4*j+1]=v.y; w0[16+4*j+2]=v.z; w0[16+4*j+3]=v.w;
        }
        q = (const float4*)(W_hh + (size_t)grow1 * HH + ok);
        #pragma unroll
        for (int j = 0; j < 4; j++) {
            float4 v = q[j];
            w1[4*j+0]=v.x; w1[4*j+1]=v.y; w1[4*j+2]=v.z; w1[4*j+3]=v.w;
        }
        q = (const float4*)(W_hh + (size_t)grow1 * HH + pk);
        #pragma unroll
        for (int j = 0; j < 4; j++) {
            float4 v = q[j];
            w1[16+4*j+0]=v.x; w1[16+4*j+1]=v.y; w1[16+4*j+2]=v.z; w1[16+4*j+3]=v.w;
        }
    }
    for (int i = tid; i < 2048; i += 512) hsm[i] = 0.0f;

    // init sync; then pre-arm for the first in-loop wait
    asm volatile("barrier.cluster.arrive.aligned;\n" ::: "memory");
    asm volatile("barrier.cluster.wait.aligned;\n" ::: "memory");
    asm volatile("barrier.cluster.arrive.aligned;\n" ::: "memory");

    // update mapping: one (col, batch) per thread
    const int ub  = tid >> 6;        // batch 0..7
    const int ucl = tid & 63;        // local col
    const int col = rank * 64 + ucl;

    float creg = 0.0f;
    int buf = 0;

    for (int s = 0; s < SS; s++) {
        const float* Hb = hsm + buf * 1024;
        float* Hn = hsm + (buf ^ 1) * 1024;

        // xp prefetch (consumed in update; overlaps both GEMM halves)
        float xv0, xv1, xv2, xv3;
        {
            const float* xpp = xp + ((size_t)(batch0 + ub) * SS + s) * GG + rank * 64 + ucl;
            xv0 = xpp[0];
            xv1 = xpp[128];
            xv2 = xpp[256];
            xv3 = xpp[384];
        }

        u64 a00 = 0, a01 = 0, a02 = 0, a03 = 0;
        u64 a10 = 0, a11 = 0, a12 = 0, a13 = 0;

        // ---- GEMM half 1: own-half k (locally produced, no barrier needed)
        #pragma unroll
        for (int kk = 0; kk < 16; kk++) {
            ulonglong2 hA = *(const ulonglong2*)(Hb + (ok + kk) * 4);        // b0..b3
            ulonglong2 hB = *(const ulonglong2*)(Hb + 512 + (ok + kk) * 4);  // b4..b7
            u64 wp0 = pack2(w0[kk]);
            u64 wp1 = pack2(w1[kk]);
            a00 = ffma2(hA.x, wp0, a00);
            a01 = ffma2(hA.y, wp0, a01);
            a02 = ffma2(hB.x, wp0, a02);
            a03 = ffma2(hB.y, wp0, a03);
            a10 = ffma2(hA.x, wp1, a10);
            a11 = ffma2(hA.y, wp1, a11);
            a12 = ffma2(hB.x, wp1, a12);
            a13 = ffma2(hB.y, wp1, a13);
        }

        // wait for peer's h half (latency hidden behind GEMM half 1)
        asm volatile("barrier.cluster.wait.aligned;\n" ::: "memory");

        // ---- GEMM half 2: peer-half k
        #pragma unroll
        for (int kk = 0; kk < 16; kk++) {
            ulonglong2 hA = *(const ulonglong2*)(Hb + (pk + kk) * 4);
            ulonglong2 hB = *(const ulonglong2*)(Hb + 512 + (pk + kk) * 4);
            u64 wp0 = pack2(w0[16 + kk]);
            u64 wp1 = pack2(w1[16 + kk]);
            a00 = ffma2(hA.x, wp0, a00);
            a01 = ffma2(hA.y, wp0, a01);
            a02 = ffma2(hB.x, wp0, a02);
            a03 = ffma2(hB.y, wp0, a03);
            a10 = ffma2(hA.x, wp1, a10);
            a11 = ffma2(hA.y, wp1, a11);
            a12 = ffma2(hB.x, wp1, a12);
            a13 = ffma2(hB.y, wp1, a13);
        }

        // write partials COALESCED: gsm[kq][b][row]
        {
            float* g0 = gsm + kq * 2048 + rr;          // row rr
            float* g1 = g0 + 128;                      // row rr+128
            float2 v;
            v = unpack2(a00); g0[0 * 256] = v.x; g0[1 * 256] = v.y;
            v = unpack2(a01); g0[2 * 256] = v.x; g0[3 * 256] = v.y;
            v = unpack2(a02); g0[4 * 256] = v.x; g0[5 * 256] = v.y;
            v = unpack2(a03); g0[6 * 256] = v.x; g0[7 * 256] = v.y;
            v = unpack2(a10); g1[0 * 256] = v.x; g1[1 * 256] = v.y;
            v = unpack2(a11); g1[2 * 256] = v.x; g1[3 * 256] = v.y;
            v = unpack2(a12); g1[4 * 256] = v.x; g1[5 * 256] = v.y;
            v = unpack2(a13); g1[6 * 256] = v.x; g1[7 * 256] = v.y;
        }
        __syncthreads();

        // ---- nonlinearity + state update: thread -> (col, batch ub)
        float hh;
        {
            float g4[4] = {xv0, xv1, xv2, xv3};
            #pragma unroll
            for (int gt = 0; gt < 4; gt++) {
                const int base = ub * 256 + gt * 64 + ucl;
                g4[gt] += gsm[base];
                g4[gt] += gsm[2048 + base];
                g4[gt] += gsm[4096 + base];
                g4[gt] += gsm[6144 + base];
            }
            float iv = sigf(g4[0]);
            float fv = sigf(g4[1]);
            float gv = tanhf_fast(g4[2]);
            float ov = sigf(g4[3]);
            creg = fmaf(fv, creg, iv * gv);
            hh = ov * tanhf_fast(creg);

            const int hoff = (ub >> 2) * 512 + col * 4 + (ub & 3);
            Hn[hoff] = hh;
            uint32_t la = (uint32_t)__cvta_generic_to_shared(Hn + hoff);
            uint32_t ra;
            asm("mapa.shared::cluster.u32 %0, %1, %2;" : "=r"(ra) : "r"(la), "r"(peer));
            asm volatile("st.shared::cluster.f32 [%0], %1;" :: "r"(ra), "f"(hh) : "memory");
        }

        // arrive (release: orders the remote h store); global store after
        asm volatile("barrier.cluster.arrive.aligned;\n" ::: "memory");

        if (store_seq) {
            hseq[((size_t)(batch0 + ub) * SS + s) * HH + col] = hh;
        } else if (s == SS - 1) {
            hlast[(batch0 + ub) * HH + col] = hh;
        }

        // order local Hn writes before next step's GEMM half 1 reads
        __syncthreads();
        buf ^= 1;
    }

    // drain the final arrive (keeps smem alive for peer's last store)
    asm volatile("barrier.cluster.wait.aligned;\n" ::: "memory");
}

// =====================================================================
// Final FC: out[b,o] = relu(h1[b,:]) @ fc_w[o,:] + fc_b[o]
// =====================================================================
__global__ __launch_bounds__(64) void fc_kernel(
    const float* __restrict__ h1, const float* __restrict__ fcw,
    const float* __restrict__ fcb, float* __restrict__ out)
{
    __shared__ float hs[HH];
    const int b = blockIdx.x;
    const int o = threadIdx.x;
    hs[o]      = fmaxf(h1[b * HH + o], 0.0f);
    hs[o + 64] = fmaxf(h1[b * HH + o + 64], 0.0f);
    __syncthreads();
    float acc = fcb[o];
    const float* wr = fcw + o * HH;
    #pragma unroll 8
    for (int k = 0; k < HH; k++)
        acc = fmaf(hs[k], wr[k], acc);
    out[b * OO + o] = acc;
}

// =====================================================================
extern "C" void kernel_launch(void* const* d_in, const int* in_sizes, int n_in,
                              void* d_out, int out_size)
{
    (void)in_sizes; (void)n_in; (void)out_size;
    const float* x     = (const float*)d_in[0];
    const float* W_ih0 = (const float*)d_in[1];
    const float* W_hh0 = (const float*)d_in[2];
    const float* b_ih0 = (const float*)d_in[3];
    const float* b_hh0 = (const float*)d_in[4];
    const float* W_ih1 = (const float*)d_in[5];
    const float* W_hh1 = (const float*)d_in[6];
    const float* b_ih1 = (const float*)d_in[7];
    const float* b_hh1 = (const float*)d_in[8];
    const float* fc_w  = (const float*)d_in[9];
    const float* fc_b  = (const float*)d_in[10];
    float* out = (float*)d_out;

    float *xp, *h0, *h1;
    cudaGetSymbolAddress((void**)&xp, g_xp);
    cudaGetSymbolAddress((void**)&h0, g_h0);
    cudaGetSymbolAddress((void**)&h1, g_h1);

    const int PROJ_SMEM = 2 * TBUF * 4 + 2 * TBUFW * 8;   // 17408 + 34816 = 52224
    const int LSTM_SMEM = (2048 + 8192) * 4;              // 40960

    cudaFuncSetAttribute(proj_kernel<FF>, cudaFuncAttributeMaxDynamicSharedMemorySize, PROJ_SMEM);
    cudaFuncSetAttribute(proj_kernel<HH>, cudaFuncAttributeMaxDynamicSharedMemorySize, PROJ_SMEM);
    cudaFuncSetAttribute(lstm_kernel, cudaFuncAttributeMaxDynamicSharedMemorySize, LSTM_SMEM);

    dim3 pgrid((BB * SS) / 128, GG / 128);

    // Layer 0
    proj_kernel<FF><<<pgrid, 256, PROJ_SMEM>>>(x, W_ih0, b_ih0, b_hh0, xp);
    lstm_kernel<<<128, 512, LSTM_SMEM>>>(xp, W_hh0, h0, nullptr, 1);

    // Layer 1
    proj_kernel<HH><<<pgrid, 256, PROJ_SMEM>>>(h0, W_ih1, b_ih1, b_hh1, xp);
    lstm_kernel<<<128, 512, LSTM_SMEM>>>(xp, W_hh1, nullptr, h1, 0);

    // FC head
    fc_kernel<<<BB, 64>>>(h1, fc_w, fc_b, out);
}

// round 12
// speedup vs baseline: 1.4947x; 1.4947x over previous
#include <cuda_runtime.h>
#include <cstdint>

typedef unsigned long long u64;

#define BB 512
#define SS 512
#define FF 64
#define HH 128
#define GG 512   // 4*H
#define OO 64

// ---- scratch (static __device__ globals: allocation-free rule) ----
__device__ float g_xp[(size_t)BB * SS * GG];   // 512 MB, reused across layers
__device__ float g_h0[(size_t)BB * SS * HH];   // 64 MB  (layer0 hidden sequence)
__device__ float g_h1[BB * HH];                // layer1 last hidden

// ---- packed f32x2 helpers (sm_103a FFMA2 path) ----
__device__ __forceinline__ u64 ffma2(u64 a, u64 b, u64 c) {
    u64 d; asm("fma.rn.f32x2 %0,%1,%2,%3;" : "=l"(d) : "l"(a), "l"(b), "l"(c)); return d;
}
__device__ __forceinline__ u64 pack2(float x) {
    u64 d; asm("mov.b64 %0,{%1,%1};" : "=l"(d) : "f"(x)); return d;
}
__device__ __forceinline__ float2 unpack2(u64 v) {
    float2 r; asm("mov.b64 {%0,%1},%2;" : "=f"(r.x), "=f"(r.y) : "l"(v)); return r;
}

__device__ __forceinline__ float sigf(float x) {
    return __fdividef(1.0f, 1.0f + __expf(-x));
}
__device__ __forceinline__ float tanhf_fast(float x) {
    return 1.0f - __fdividef(2.0f, __expf(2.0f * x) + 1.0f);
}

// =====================================================================
// Projection GEMM (FFMA2, 3 CTAs/SM, 6 warps/SMSP):
// out[M,512] = A[M,K] @ W[512,K]^T + ba + bb
// Tile 128m x 64n, 16-k double-buffered chunks.
// grid = (M/128, 8), block = 256 (thread = 8m x 4n, ~70 regs).
// SMEM: smA[2][16][136], smW[2][16][72]
// =====================================================================
#define KPA 136
#define KPW 72
#define TBA (16 * KPA)   // 2176 floats
#define TBW (16 * KPW)   // 1152 floats

template <int K>
__global__ __launch_bounds__(256, 3) void proj_kernel(
    const float* __restrict__ A, const float* __restrict__ W,
    const float* __restrict__ ba, const float* __restrict__ bb,
    float* __restrict__ out)
{
    extern __shared__ float sm[];
    float* smA = sm;               // 2 x TBA
    float* smW = sm + 2 * TBA;     // 2 x TBW

    const int tid = threadIdx.x;
    const int m0 = blockIdx.x * 128;
    const int n0 = blockIdx.y * 64;
    const int NC = K / 16;

    // A fill mapping: thread -> (row ar, k-quads aq, aq+1)
    const int ar = tid & 127;
    const int aq = (tid >> 7) * 2;
    // W fill mapping: thread -> (row wr, k-quad wq)
    const int wr = tid & 63;
    const int wq = tid >> 6;

    // ---- chunk 0 fill
    {
        float4 a0 = *(const float4*)(A + (size_t)(m0 + ar) * K + aq * 4);
        float4 a1 = *(const float4*)(A + (size_t)(m0 + ar) * K + (aq + 1) * 4);
        float4 w0 = *(const float4*)(W + (size_t)(n0 + wr) * K + wq * 4);
        #pragma unroll
        for (int j = 0; j < 4; j++) {
            float av0 = (j==0)?a0.x:(j==1)?a0.y:(j==2)?a0.z:a0.w;
            float av1 = (j==0)?a1.x:(j==1)?a1.y:(j==2)?a1.z:a1.w;
            float wv  = (j==0)?w0.x:(j==1)?w0.y:(j==2)?w0.z:w0.w;
            smA[(aq * 4 + j) * KPA + ar]       = av0;
            smA[((aq + 1) * 4 + j) * KPA + ar] = av1;
            smW[(wq * 4 + j) * KPW + wr]       = wv;
        }
    }
    __syncthreads();

    const int mb = (tid >> 4) * 8;   // m-octet (broadcast within warp: 2 values)
    const int nb = (tid & 15) * 4;   // n-quad

    u64 acc[4][4];
    #pragma unroll
    for (int p = 0; p < 4; p++)
        #pragma unroll
        for (int j = 0; j < 4; j++) acc[p][j] = 0ull;

    int buf = 0;
    for (int c = 0; c < NC; c++) {
        float4 pa0, pa1, pw0;
        const bool pf = (c + 1 < NC);
        if (pf) {
            const int k0 = (c + 1) * 16;
            pa0 = *(const float4*)(A + (size_t)(m0 + ar) * K + k0 + aq * 4);
            pa1 = *(const float4*)(A + (size_t)(m0 + ar) * K + k0 + (aq + 1) * 4);
            pw0 = *(const float4*)(W + (size_t)(n0 + wr) * K + k0 + wq * 4);
        }

        const float* bA = smA + buf * TBA;
        const float* bW = smW + buf * TBW;
        #pragma unroll
        for (int kk = 0; kk < 16; kk++) {
            ulonglong2 aA = *(const ulonglong2*)(bA + kk * KPA + mb);      // m0..m3 pairs
            ulonglong2 aB = *(const ulonglong2*)(bA + kk * KPA + mb + 4);  // m4..m7 pairs
            float4 w = *(const float4*)(bW + kk * KPW + nb);
            u64 ap[4] = {aA.x, aA.y, aB.x, aB.y};
            float wf[4] = {w.x, w.y, w.z, w.w};
            #pragma unroll
            for (int j = 0; j < 4; j++) {
                u64 wp = pack2(wf[j]);
                #pragma unroll
                for (int p = 0; p < 4; p++)
                    acc[p][j] = ffma2(ap[p], wp, acc[p][j]);
            }
        }

        if (pf) {
            float* dA = smA + (buf ^ 1) * TBA;
            float* dW = smW + (buf ^ 1) * TBW;
            #pragma unroll
            for (int j = 0; j < 4; j++) {
                float av0 = (j==0)?pa0.x:(j==1)?pa0.y:(j==2)?pa0.z:pa0.w;
                float av1 = (j==0)?pa1.x:(j==1)?pa1.y:(j==2)?pa1.z:pa1.w;
                float wv  = (j==0)?pw0.x:(j==1)?pw0.y:(j==2)?pw0.z:pw0.w;
                dA[(aq * 4 + j) * KPA + ar]       = av0;
                dA[((aq + 1) * 4 + j) * KPA + ar] = av1;
                dW[(wq * 4 + j) * KPW + wr]       = wv;
            }
        }
        __syncthreads();
        buf ^= 1;
    }

    float bias[4];
    #pragma unroll
    for (int j = 0; j < 4; j++)
        bias[j] = ba[n0 + nb + j] + bb[n0 + nb + j];

    #pragma unroll
    for (int p = 0; p < 4; p++) {
        float r0[4], r1[4];
        #pragma unroll
        for (int j = 0; j < 4; j++) {
            float2 v = unpack2(acc[p][j]);
            r0[j] = v.x + bias[j];
            r1[j] = v.y + bias[j];
        }
        float* o0 = out + (size_t)(m0 + mb + 2 * p) * GG + n0 + nb;
        float* o1 = o0 + GG;
        *(float4*)(o0) = make_float4(r0[0], r0[1], r0[2], r0[3]);
        *(float4*)(o1) = make_float4(r1[0], r1[1], r1[2], r1[3]);
    }
}

// =====================================================================
// Recurrent LSTM layer (R9, unchanged — best measured: ~1.28 ms/layer).
// split-k GEMM around the cluster barrier; cluster = 2 CTAs, 8 batch
// rows; CTA owns 64 hidden cols (256 gate rows). Thread = 2 rows x
// (16 own k + 16 peer k), 64 W regs. gsm coalesced. 128 CTAs x 512.
// =====================================================================
__global__ void __cluster_dims__(2, 1, 1) __launch_bounds__(512, 1) lstm_kernel(
    const float* __restrict__ xp,    // [B, S, 4H]
    const float* __restrict__ W_hh,  // [4H, H]
    float* __restrict__ hseq,        // [B, S, H]  (layer 0)
    float* __restrict__ hlast,       // [B, H]     (layer 1)
    int store_seq)
{
    extern __shared__ float sm[];
    float* hsm = sm;          // 2 x [2 grp][128 k][4 b] = 2 x 1024
    float* gsm = sm + 2048;   // [4 kq][8 b][256 row] = 8192

    const int tid    = threadIdx.x;
    const int rank   = blockIdx.x & 1;
    const int peer   = rank ^ 1;
    const int batch0 = (blockIdx.x >> 1) * 8;

    const int kq = tid >> 7;         // k-segment 0..3 (16 k within each half)
    const int rr = tid & 127;        // local row-pair id
    const int grow0 = (rr >> 6) * 128 + rank * 64 + (rr & 63);
    const int grow1 = grow0 + 256;

    const int ok = rank * 64 + kq * 16;   // own-half k base
    const int pk = peer * 64 + kq * 16;   // peer-half k base

    // ---- W into registers: [0..15] own-half k, [16..31] peer-half k
    float w0[32], w1[32];
    {
        const float4* q;
        q = (const float4*)(W_hh + (size_t)grow0 * HH + ok);
        #pragma unroll
        for (int j = 0; j < 4; j++) {
            float4 v = q[j];
            w0[4*j+0]=v.x; w0[4*j+1]=v.y; w0[4*j+2]=v.z; w0[4*j+3]=v.w;
        }
        q = (const float4*)(W_hh + (size_t)grow0 * HH + pk);
        #pragma unroll
        for (int j = 0; j < 4; j++) {
            float4 v = q[j];
            w0[16+4*j+0]=v.x; w0[16+4*j+1]=v.y; w0[16+4*j+2]=v.z; w0[16+4*j+3]=v.w;
        }
        q = (const float4*)(W_hh + (size_t)grow1 * HH + ok);
        #pragma unroll
        for (int j = 0; j < 4; j++) {
            float4 v = q[j];
            w1[4*j+0]=v.x; w1[4*j+1]=v.y; w1[4*j+2]=v.z; w1[4*j+3]=v.w;
        }
        q = (const float4*)(W_hh + (size_t)grow1 * HH + pk);
        #pragma unroll
        for (int j = 0; j < 4; j++) {
            float4 v = q[j];
            w1[16+4*j+0]=v.x; w1[16+4*j+1]=v.y; w1[16+4*j+2]=v.z; w1[16+4*j+3]=v.w;
        }
    }
    for (int i = tid; i < 2048; i += 512) hsm[i] = 0.0f;

    // init sync; then pre-arm for the first in-loop wait
    asm volatile("barrier.cluster.arrive.aligned;\n" ::: "memory");
    asm volatile("barrier.cluster.wait.aligned;\n" ::: "memory");
    asm volatile("barrier.cluster.arrive.aligned;\n" ::: "memory");

    // update mapping: one (col, batch) per thread
    const int ub  = tid >> 6;        // batch 0..7
    const int ucl = tid & 63;        // local col
    const int col = rank * 64 + ucl;

    float creg = 0.0f;
    int buf = 0;

    for (int s = 0; s < SS; s++) {
        const float* Hb = hsm + buf * 1024;
        float* Hn = hsm + (buf ^ 1) * 1024;

        // xp prefetch (consumed in update; overlaps both GEMM halves)
        float xv0, xv1, xv2, xv3;
        {
            const float* xpp = xp + ((size_t)(batch0 + ub) * SS + s) * GG + rank * 64 + ucl;
            xv0 = xpp[0];
            xv1 = xpp[128];
            xv2 = xpp[256];
            xv3 = xpp[384];
        }

        u64 a00 = 0, a01 = 0, a02 = 0, a03 = 0;
        u64 a10 = 0, a11 = 0, a12 = 0, a13 = 0;

        // ---- GEMM half 1: own-half k (locally produced, no barrier needed)
        #pragma unroll
        for (int kk = 0; kk < 16; kk++) {
            ulonglong2 hA = *(const ulonglong2*)(Hb + (ok + kk) * 4);        // b0..b3
            ulonglong2 hB = *(const ulonglong2*)(Hb + 512 + (ok + kk) * 4);  // b4..b7
            u64 wp0 = pack2(w0[kk]);
            u64 wp1 = pack2(w1[kk]);
            a00 = ffma2(hA.x, wp0, a00);
            a01 = ffma2(hA.y, wp0, a01);
            a02 = ffma2(hB.x, wp0, a02);
            a03 = ffma2(hB.y, wp0, a03);
            a10 = ffma2(hA.x, wp1, a10);
            a11 = ffma2(hA.y, wp1, a11);
            a12 = ffma2(hB.x, wp1, a12);
            a13 = ffma2(hB.y, wp1, a13);
        }

        // wait for peer's h half (latency hidden behind GEMM half 1)
        asm volatile("barrier.cluster.wait.aligned;\n" ::: "memory");

        // ---- GEMM half 2: peer-half k
        #pragma unroll
        for (int kk = 0; kk < 16; kk++) {
            ulonglong2 hA = *(const ulonglong2*)(Hb + (pk + kk) * 4);
            ulonglong2 hB = *(const ulonglong2*)(Hb + 512 + (pk + kk) * 4);
            u64 wp0 = pack2(w0[16 + kk]);
            u64 wp1 = pack2(w1[16 + kk]);
            a00 = ffma2(hA.x, wp0, a00);
            a01 = ffma2(hA.y, wp0, a01);
            a02 = ffma2(hB.x, wp0, a02);
            a03 = ffma2(hB.y, wp0, a03);
            a10 = ffma2(hA.x, wp1, a10);
            a11 = ffma2(hA.y, wp1, a11);
            a12 = ffma2(hB.x, wp1, a12);
            a13 = ffma2(hB.y, wp1, a13);
        }

        // write partials COALESCED: gsm[kq][b][row]
        {
            float* g0 = gsm + kq * 2048 + rr;          // row rr
            float* g1 = g0 + 128;                      // row rr+128
            float2 v;
            v = unpack2(a00); g0[0 * 256] = v.x; g0[1 * 256] = v.y;
            v = unpack2(a01); g0[2 * 256] = v.x; g0[3 * 256] = v.y;
            v = unpack2(a02); g0[4 * 256] = v.x; g0[5 * 256] = v.y;
            v = unpack2(a03); g0[6 * 256] = v.x; g0[7 * 256] = v.y;
            v = unpack2(a10); g1[0 * 256] = v.x; g1[1 * 256] = v.y;
            v = unpack2(a11); g1[2 * 256] = v.x; g1[3 * 256] = v.y;
            v = unpack2(a12); g1[4 * 256] = v.x; g1[5 * 256] = v.y;
            v = unpack2(a13); g1[6 * 256] = v.x; g1[7 * 256] = v.y;
        }
        __syncthreads();

        // ---- nonlinearity + state update: thread -> (col, batch ub)
        float hh;
        {
            float g4[4] = {xv0, xv1, xv2, xv3};
            #pragma unroll
            for (int gt = 0; gt < 4; gt++) {
                const int base = ub * 256 + gt * 64 + ucl;
                g4[gt] += gsm[base];
                g4[gt] += gsm[2048 + base];
                g4[gt] += gsm[4096 + base];
                g4[gt] += gsm[6144 + base];
            }
            float iv = sigf(g4[0]);
            float fv = sigf(g4[1]);
            float gv = tanhf_fast(g4[2]);
            float ov = sigf(g4[3]);
            creg = fmaf(fv, creg, iv * gv);
            hh = ov * tanhf_fast(creg);

            const int hoff = (ub >> 2) * 512 + col * 4 + (ub & 3);
            Hn[hoff] = hh;
            uint32_t la = (uint32_t)__cvta_generic_to_shared(Hn + hoff);
            uint32_t ra;
            asm("mapa.shared::cluster.u32 %0, %1, %2;" : "=r"(ra) : "r"(la), "r"(peer));
            asm volatile("st.shared::cluster.f32 [%0], %1;" :: "r"(ra), "f"(hh) : "memory");
        }

        // arrive (release: orders the remote h store); global store after
        asm volatile("barrier.cluster.arrive.aligned;\n" ::: "memory");

        if (store_seq) {
            hseq[((size_t)(batch0 + ub) * SS + s) * HH + col] = hh;
        } else if (s == SS - 1) {
            hlast[(batch0 + ub) * HH + col] = hh;
        }

        // order local Hn writes before next step's GEMM half 1 reads
        __syncthreads();
        buf ^= 1;
    }

    // drain the final arrive (keeps smem alive for peer's last store)
    asm volatile("barrier.cluster.wait.aligned;\n" ::: "memory");
}

// =====================================================================
// Final FC: out[b,o] = relu(h1[b,:]) @ fc_w[o,:] + fc_b[o]
// =====================================================================
__global__ __launch_bounds__(64) void fc_kernel(
    const float* __restrict__ h1, const float* __restrict__ fcw,
    const float* __restrict__ fcb, float* __restrict__ out)
{
    __shared__ float hs[HH];
    const int b = blockIdx.x;
    const int o = threadIdx.x;
    hs[o]      = fmaxf(h1[b * HH + o], 0.0f);
    hs[o + 64] = fmaxf(h1[b * HH + o + 64], 0.0f);
    __syncthreads();
    float acc = fcb[o];
    const float* wr = fcw + o * HH;
    #pragma unroll 8
    for (int k = 0; k < HH; k++)
        acc = fmaf(hs[k], wr[k], acc);
    out[b * OO + o] = acc;
}

// =====================================================================
extern "C" void kernel_launch(void* const* d_in, const int* in_sizes, int n_in,
                              void* d_out, int out_size)
{
    (void)in_sizes; (void)n_in; (void)out_size;
    const float* x     = (const float*)d_in[0];
    const float* W_ih0 = (const float*)d_in[1];
    const float* W_hh0 = (const float*)d_in[2];
    const float* b_ih0 = (const float*)d_in[3];
    const float* b_hh0 = (const float*)d_in[4];
    const float* W_ih1 = (const float*)d_in[5];
    const float* W_hh1 = (const float*)d_in[6];
    const float* b_ih1 = (const float*)d_in[7];
    const float* b_hh1 = (const float*)d_in[8];
    const float* fc_w  = (const float*)d_in[9];
    const float* fc_b  = (const float*)d_in[10];
    float* out = (float*)d_out;

    float *xp, *h0, *h1;
    cudaGetSymbolAddress((void**)&xp, g_xp);
    cudaGetSymbolAddress((void**)&h0, g_h0);
    cudaGetSymbolAddress((void**)&h1, g_h1);

    const int PROJ_SMEM = (2 * TBA + 2 * TBW) * 4;   // (4352+2304)*4 = 26624
    const int LSTM_SMEM = (2048 + 8192) * 4;         // 40960

    cudaFuncSetAttribute(proj_kernel<FF>, cudaFuncAttributeMaxDynamicSharedMemorySize, PROJ_SMEM);
    cudaFuncSetAttribute(proj_kernel<HH>, cudaFuncAttributeMaxDynamicSharedMemorySize, PROJ_SMEM);
    cudaFuncSetAttribute(lstm_kernel, cudaFuncAttributeMaxDynamicSharedMemorySize, LSTM_SMEM);

    dim3 pgrid((BB * SS) / 128, GG / 64);

    // Layer 0
    proj_kernel<FF><<<pgrid, 256, PROJ_SMEM>>>(x, W_ih0, b_ih0, b_hh0, xp);
    lstm_kernel<<<128, 512, LSTM_SMEM>>>(xp, W_hh0, h0, nullptr, 1);

    // Layer 1
    proj_kernel<HH><<<pgrid, 256, PROJ_SMEM>>>(h0, W_ih1, b_ih1, b_hh1, xp);
    lstm_kernel<<<128, 512, LSTM_SMEM>>>(xp, W_hh1, nullptr, h1, 0);

    // FC head
    fc_kernel<<<BB, 64>>>(h1, fc_w, fc_b, out);
}

// round 14
// speedup vs baseline: 1.5095x; 1.0099x over previous
#include <cuda_runtime.h>
#include <cstdint>

typedef unsigned long long u64;

#define BB 512
#define SS 512
#define FF 64
#define HH 128
#define GG 512   // 4*H
#define OO 64

// ---- scratch (static __device__ globals: allocation-free rule) ----
__device__ float g_xp[(size_t)BB * SS * GG];   // 512 MB, reused across layers
__device__ float g_h0[(size_t)BB * SS * HH];   // 64 MB  (layer0 hidden sequence)
__device__ float g_h1[BB * HH];                // layer1 last hidden

// ---- packed f32x2 helpers (sm_103a FFMA2 path) ----
__device__ __forceinline__ u64 ffma2(u64 a, u64 b, u64 c) {
    u64 d; asm("fma.rn.f32x2 %0,%1,%2,%3;" : "=l"(d) : "l"(a), "l"(b), "l"(c)); return d;
}
__device__ __forceinline__ u64 pack2(float x) {
    u64 d; asm("mov.b64 %0,{%1,%1};" : "=l"(d) : "f"(x)); return d;
}
__device__ __forceinline__ float2 unpack2(u64 v) {
    float2 r; asm("mov.b64 {%0,%1},%2;" : "=f"(r.x), "=f"(r.y) : "l"(v)); return r;
}

__device__ __forceinline__ float sigf(float x) {
    return __fdividef(1.0f, 1.0f + __expf(-x));
}
__device__ __forceinline__ float tanhf_fast(float x) {
    return 1.0f - __fdividef(2.0f, __expf(2.0f * x) + 1.0f);
}

// =====================================================================
// Projection GEMM (FFMA2, double-buffered 16-k chunks, 2 CTAs/SM):
// out[M,512] = A[M,K] @ W[512,K]^T + ba + bb
// 1D grid, n-fast: 4 consecutive CTAs share one A tile (L2 reuse).
// block = 256 (thread = 8m x 8n). Bias LDGs hoisted before main loop.
// =====================================================================
#define KPAD 136
#define TBUF (16 * KPAD)   // 2176 floats per buffer

template <int K>
__global__ __launch_bounds__(256, 2) void proj_kernel(
    const float* __restrict__ A, const float* __restrict__ W,
    const float* __restrict__ ba, const float* __restrict__ bb,
    float* __restrict__ out)
{
    extern __shared__ float sm[];
    float* smA = sm;               // 2 x TBUF
    float* smW = sm + 2 * TBUF;    // 2 x TBUF

    const int tid = threadIdx.x;
    // n-fast linearized grid: 4 CTAs with consecutive bx share the A tile
    const int m0 = (blockIdx.x >> 2) * 128;
    const int n0 = (blockIdx.x & 3) * 128;
    const int NC = K / 16;

    const int rl = tid >> 2;       // load row 0..63
    const int k4 = tid & 3;        // k-quad within chunk

    const int mb = (tid >> 4) * 8;   // m-octet
    const int nb = (tid & 15) * 8;   // n-octet

    // bias LDGs issued early; latency hidden under the main loop
    float bias[8];
    #pragma unroll
    for (int j = 0; j < 8; j++)
        bias[j] = ba[n0 + nb + j] + bb[n0 + nb + j];

    {
        float4 a0 = *(const float4*)(A + (size_t)(m0 + rl) * K + k4 * 4);
        float4 a1 = *(const float4*)(A + (size_t)(m0 + rl + 64) * K + k4 * 4);
        float4 w0 = *(const float4*)(W + (size_t)(n0 + rl) * K + k4 * 4);
        float4 w1 = *(const float4*)(W + (size_t)(n0 + rl + 64) * K + k4 * 4);
        #pragma unroll
        for (int j = 0; j < 4; j++) {
            float av0 = (j==0)?a0.x:(j==1)?a0.y:(j==2)?a0.z:a0.w;
            float av1 = (j==0)?a1.x:(j==1)?a1.y:(j==2)?a1.z:a1.w;
            float wv0 = (j==0)?w0.x:(j==1)?w0.y:(j==2)?w0.z:w0.w;
            float wv1 = (j==0)?w1.x:(j==1)?w1.y:(j==2)?w1.z:w1.w;
            smA[(k4*4+j)*KPAD + rl]      = av0;
            smA[(k4*4+j)*KPAD + rl + 64] = av1;
            smW[(k4*4+j)*KPAD + rl]      = wv0;
            smW[(k4*4+j)*KPAD + rl + 64] = wv1;
        }
    }
    __syncthreads();

    u64 acc[4][8];
    #pragma unroll
    for (int p = 0; p < 4; p++)
        #pragma unroll
        for (int j = 0; j < 8; j++) acc[p][j] = 0ull;

    int buf = 0;
    for (int c = 0; c < NC; c++) {
        float4 pa0, pa1, pw0, pw1;
        const bool pf = (c + 1 < NC);
        if (pf) {
            const int k0 = (c + 1) * 16;
            pa0 = *(const float4*)(A + (size_t)(m0 + rl) * K + k0 + k4 * 4);
            pa1 = *(const float4*)(A + (size_t)(m0 + rl + 64) * K + k0 + k4 * 4);
            pw0 = *(const float4*)(W + (size_t)(n0 + rl) * K + k0 + k4 * 4);
            pw1 = *(const float4*)(W + (size_t)(n0 + rl + 64) * K + k0 + k4 * 4);
        }

        const float* bA = smA + buf * TBUF;
        const float* bW = smW + buf * TBUF;
        #pragma unroll
        for (int kk = 0; kk < 16; kk++) {
            ulonglong2 aA = *(const ulonglong2*)(bA + kk * KPAD + mb);
            ulonglong2 aB = *(const ulonglong2*)(bA + kk * KPAD + mb + 4);
            float4 w0 = *(const float4*)(bW + kk * KPAD + nb);
            float4 w1 = *(const float4*)(bW + kk * KPAD + nb + 4);
            u64 ap[4] = {aA.x, aA.y, aB.x, aB.y};
            float wf[8] = {w0.x, w0.y, w0.z, w0.w, w1.x, w1.y, w1.z, w1.w};
            #pragma unroll
            for (int j = 0; j < 8; j++) {
                u64 wp = pack2(wf[j]);
                #pragma unroll
                for (int p = 0; p < 4; p++)
                    acc[p][j] = ffma2(ap[p], wp, acc[p][j]);
            }
        }

        if (pf) {
            float* dA = smA + (buf ^ 1) * TBUF;
            float* dW = smW + (buf ^ 1) * TBUF;
            #pragma unroll
            for (int j = 0; j < 4; j++) {
                float av0 = (j==0)?pa0.x:(j==1)?pa0.y:(j==2)?pa0.z:pa0.w;
                float av1 = (j==0)?pa1.x:(j==1)?pa1.y:(j==2)?pa1.z:pa1.w;
                float wv0 = (j==0)?pw0.x:(j==1)?pw0.y:(j==2)?pw0.z:pw0.w;
                float wv1 = (j==0)?pw1.x:(j==1)?pw1.y:(j==2)?pw1.z:pw1.w;
                dA[(k4*4+j)*KPAD + rl]      = av0;
                dA[(k4*4+j)*KPAD + rl + 64] = av1;
                dW[(k4*4+j)*KPAD + rl]      = wv0;
                dW[(k4*4+j)*KPAD + rl + 64] = wv1;
            }
        }
        __syncthreads();
        buf ^= 1;
    }

    #pragma unroll
    for (int p = 0; p < 4; p++) {
        float r0[8], r1[8];
        #pragma unroll
        for (int j = 0; j < 8; j++) {
            float2 v = unpack2(acc[p][j]);
            r0[j] = v.x + bias[j];
            r1[j] = v.y + bias[j];
        }
        float* o0 = out + (size_t)(m0 + mb + 2 * p) * GG + n0 + nb;
        float* o1 = o0 + GG;
        *(float4*)(o0)     = make_float4(r0[0], r0[1], r0[2], r0[3]);
        *(float4*)(o0 + 4) = make_float4(r0[4], r0[5], r0[6], r0[7]);
        *(float4*)(o1)     = make_float4(r1[0], r1[1], r1[2], r1[3]);
        *(float4*)(o1 + 4) = make_float4(r1[4], r1[5], r1[6], r1[7]);
    }
}

// =====================================================================
// Recurrent LSTM layer (R9, best measured: ~1.28 ms/layer).
// split-k GEMM around the cluster barrier; cluster = 2 CTAs, 8 batch
// rows; CTA owns 64 hidden cols (256 gate rows). Thread = 2 rows x
// (16 own k + 16 peer k), 64 W regs. gsm coalesced. 128 CTAs x 512.
// =====================================================================
__global__ void __cluster_dims__(2, 1, 1) __launch_bounds__(512, 1) lstm_kernel(
    const float* __restrict__ xp,    // [B, S, 4H]
    const float* __restrict__ W_hh,  // [4H, H]
    float* __restrict__ hseq,        // [B, S, H]  (layer 0)
    float* __restrict__ hlast,       // [B, H]     (layer 1)
    int store_seq)
{
    extern __shared__ float sm[];
    float* hsm = sm;          // 2 x [2 grp][128 k][4 b] = 2 x 1024
    float* gsm = sm + 2048;   // [4 kq][8 b][256 row] = 8192

    const int tid    = threadIdx.x;
    const int rank   = blockIdx.x & 1;
    const int peer   = rank ^ 1;
    const int batch0 = (blockIdx.x >> 1) * 8;

    const int kq = tid >> 7;         // k-segment 0..3 (16 k within each half)
    const int rr = tid & 127;        // local row-pair id
    const int grow0 = (rr >> 6) * 128 + rank * 64 + (rr & 63);
    const int grow1 = grow0 + 256;

    const int ok = rank * 64 + kq * 16;   // own-half k base
    const int pk = peer * 64 + kq * 16;   // peer-half k base

    // ---- W into registers: [0..15] own-half k, [16..31] peer-half k
    float w0[32], w1[32];
    {
        const float4* q;
        q = (const float4*)(W_hh + (size_t)grow0 * HH + ok);
        #pragma unroll
        for (int j = 0; j < 4; j++) {
            float4 v = q[j];
            w0[4*j+0]=v.x; w0[4*j+1]=v.y; w0[4*j+2]=v.z; w0[4*j+3]=v.w;
        }
        q = (const float4*)(W_hh + (size_t)grow0 * HH + pk);
        #pragma unroll
        for (int j = 0; j < 4; j++) {
            float4 v = q[j];
            w0[16+4*j+0]=v.x; w0[16+4*j+1]=v.y; w0[16+4*j+2]=v.z; w0[16+4*j+3]=v.w;
        }
        q = (const float4*)(W_hh + (size_t)grow1 * HH + ok);
        #pragma unroll
        for (int j = 0; j < 4; j++) {
            float4 v = q[j];
            w1[4*j+0]=v.x; w1[4*j+1]=v.y; w1[4*j+2]=v.z; w1[4*j+3]=v.w;
        }
        q = (const float4*)(W_hh + (size_t)grow1 * HH + pk);
        #pragma unroll
        for (int j = 0; j < 4; j++) {
            float4 v = q[j];
            w1[16+4*j+0]=v.x; w1[16+4*j+1]=v.y; w1[16+4*j+2]=v.z; w1[16+4*j+3]=v.w;
        }
    }
    for (int i = tid; i < 2048; i += 512) hsm[i] = 0.0f;

    // init sync; then pre-arm for the first in-loop wait
    asm volatile("barrier.cluster.arrive.aligned;\n" ::: "memory");
    asm volatile("barrier.cluster.wait.aligned;\n" ::: "memory");
    asm volatile("barrier.cluster.arrive.aligned;\n" ::: "memory");

    // update mapping: one (col, batch) per thread
    const int ub  = tid >> 6;        // batch 0..7
    const int ucl = tid & 63;        // local col
    const int col = rank * 64 + ucl;

    float creg = 0.0f;
    int buf = 0;

    for (int s = 0; s < SS; s++) {
        const float* Hb = hsm + buf * 1024;
        float* Hn = hsm + (buf ^ 1) * 1024;

        // xp prefetch (consumed in update; overlaps both GEMM halves)
        float xv0, xv1, xv2, xv3;
        {
            const float* xpp = xp + ((size_t)(batch0 + ub) * SS + s) * GG + rank * 64 + ucl;
            xv0 = xpp[0];
            xv1 = xpp[128];
            xv2 = xpp[256];
            xv3 = xpp[384];
        }

        u64 a00 = 0, a01 = 0, a02 = 0, a03 = 0;
        u64 a10 = 0, a11 = 0, a12 = 0, a13 = 0;

        // ---- GEMM half 1: own-half k (locally produced, no barrier needed)
        #pragma unroll
        for (int kk = 0; kk < 16; kk++) {
            ulonglong2 hA = *(const ulonglong2*)(Hb + (ok + kk) * 4);        // b0..b3
            ulonglong2 hB = *(const ulonglong2*)(Hb + 512 + (ok + kk) * 4);  // b4..b7
            u64 wp0 = pack2(w0[kk]);
            u64 wp1 = pack2(w1[kk]);
            a00 = ffma2(hA.x, wp0, a00);
            a01 = ffma2(hA.y, wp0, a01);
            a02 = ffma2(hB.x, wp0, a02);
            a03 = ffma2(hB.y, wp0, a03);
            a10 = ffma2(hA.x, wp1, a10);
            a11 = ffma2(hA.y, wp1, a11);
            a12 = ffma2(hB.x, wp1, a12);
            a13 = ffma2(hB.y, wp1, a13);
        }

        // wait for peer's h half (latency hidden behind GEMM half 1)
        asm volatile("barrier.cluster.wait.aligned;\n" ::: "memory");

        // ---- GEMM half 2: peer-half k
        #pragma unroll
        for (int kk = 0; kk < 16; kk++) {
            ulonglong2 hA = *(const ulonglong2*)(Hb + (pk + kk) * 4);
            ulonglong2 hB = *(const ulonglong2*)(Hb + 512 + (pk + kk) * 4);
            u64 wp0 = pack2(w0[16 + kk]);
            u64 wp1 = pack2(w1[16 + kk]);
            a00 = ffma2(hA.x, wp0, a00);
            a01 = ffma2(hA.y, wp0, a01);
            a02 = ffma2(hB.x, wp0, a02);
            a03 = ffma2(hB.y, wp0, a03);
            a10 = ffma2(hA.x, wp1, a10);
            a11 = ffma2(hA.y, wp1, a11);
            a12 = ffma2(hB.x, wp1, a12);
            a13 = ffma2(hB.y, wp1, a13);
        }

        // write partials COALESCED: gsm[kq][b][row]
        {
            float* g0 = gsm + kq * 2048 + rr;          // row rr
            float* g1 = g0 + 128;                      // row rr+128
            float2 v;
            v = unpack2(a00); g0[0 * 256] = v.x; g0[1 * 256] = v.y;
            v = unpack2(a01); g0[2 * 256] = v.x; g0[3 * 256] = v.y;
            v = unpack2(a02); g0[4 * 256] = v.x; g0[5 * 256] = v.y;
            v = unpack2(a03); g0[6 * 256] = v.x; g0[7 * 256] = v.y;
            v = unpack2(a10); g1[0 * 256] = v.x; g1[1 * 256] = v.y;
            v = unpack2(a11); g1[2 * 256] = v.x; g1[3 * 256] = v.y;
            v = unpack2(a12); g1[4 * 256] = v.x; g1[5 * 256] = v.y;
            v = unpack2(a13); g1[6 * 256] = v.x; g1[7 * 256] = v.y;
        }
        __syncthreads();

        // ---- nonlinearity + state update: thread -> (col, batch ub)
        float hh;
        {
            float g4[4] = {xv0, xv1, xv2, xv3};
            #pragma unroll
            for (int gt = 0; gt < 4; gt++) {
                const int base = ub * 256 + gt * 64 + ucl;
                g4[gt] += gsm[base];
                g4[gt] += gsm[2048 + base];
                g4[gt] += gsm[4096 + base];
                g4[gt] += gsm[6144 + base];
            }
            float iv = sigf(g4[0]);
            float fv = sigf(g4[1]);
            float gv = tanhf_fast(g4[2]);
            float ov = sigf(g4[3]);
            creg = fmaf(fv, creg, iv * gv);
            hh = ov * tanhf_fast(creg);

            const int hoff = (ub >> 2) * 512 + col * 4 + (ub & 3);
            Hn[hoff] = hh;
            uint32_t la = (uint32_t)__cvta_generic_to_shared(Hn + hoff);
            uint32_t ra;
            asm("mapa.shared::cluster.u32 %0, %1, %2;" : "=r"(ra) : "r"(la), "r"(peer));
            asm volatile("st.shared::cluster.f32 [%0], %1;" :: "r"(ra), "f"(hh) : "memory");
        }

        // arrive (release: orders the remote h store); global store after
        asm volatile("barrier.cluster.arrive.aligned;\n" ::: "memory");

        if (store_seq) {
            hseq[((size_t)(batch0 + ub) * SS + s) * HH + col] = hh;
        } else if (s == SS - 1) {
            hlast[(batch0 + ub) * HH + col] = hh;
        }

        // order local Hn writes before next step's GEMM half 1 reads
        __syncthreads();
        buf ^= 1;
    }

    // drain the final arrive (keeps smem alive for peer's last store)
    asm volatile("barrier.cluster.wait.aligned;\n" ::: "memory");
}

// =====================================================================
// Final FC: out[b,o] = relu(h1[b,:]) @ fc_w[o,:] + fc_b[o]
// =====================================================================
__global__ __launch_bounds__(64) void fc_kernel(
    const float* __restrict__ h1, const float* __restrict__ fcw,
    const float* __restrict__ fcb, float* __restrict__ out)
{
    __shared__ float hs[HH];
    const int b = blockIdx.x;
    const int o = threadIdx.x;
    hs[o]      = fmaxf(h1[b * HH + o], 0.0f);
    hs[o + 64] = fmaxf(h1[b * HH + o + 64], 0.0f);
    __syncthreads();
    float acc = fcb[o];
    const float* wr = fcw + o * HH;
    #pragma unroll 8
    for (int k = 0; k < HH; k++)
        acc = fmaf(hs[k], wr[k], acc);
    out[b * OO + o] = acc;
}

// =====================================================================
extern "C" void kernel_launch(void* const* d_in, const int* in_sizes, int n_in,
                              void* d_out, int out_size)
{
    (void)in_sizes; (void)n_in; (void)out_size;
    const float* x     = (const float*)d_in[0];
    const float* W_ih0 = (const float*)d_in[1];
    const float* W_hh0 = (const float*)d_in[2];
    const float* b_ih0 = (const float*)d_in[3];
    const float* b_hh0 = (const float*)d_in[4];
    const float* W_ih1 = (const float*)d_in[5];
    const float* W_hh1 = (const float*)d_in[6];
    const float* b_ih1 = (const float*)d_in[7];
    const float* b_hh1 = (const float*)d_in[8];
    const float* fc_w  = (const float*)d_in[9];
    const float* fc_b  = (const float*)d_in[10];
    float* out = (float*)d_out;

    float *xp, *h0, *h1;
    cudaGetSymbolAddress((void**)&xp, g_xp);
    cudaGetSymbolAddress((void**)&h0, g_h0);
    cudaGetSymbolAddress((void**)&h1, g_h1);

    const int PROJ_SMEM = 4 * TBUF * 4;             // 34816
    const int LSTM_SMEM = (2048 + 8192) * 4;        // 40960

    cudaFuncSetAttribute(proj_kernel<FF>, cudaFuncAttributeMaxDynamicSharedMemorySize, PROJ_SMEM);
    cudaFuncSetAttribute(proj_kernel<HH>, cudaFuncAttributeMaxDynamicSharedMemorySize, PROJ_SMEM);
    cudaFuncSetAttribute(lstm_kernel, cudaFuncAttributeMaxDynamicSharedMemorySize, LSTM_SMEM);

    const int pgrid = ((BB * SS) / 128) * (GG / 128);   // 8192, n-fast

    // Layer 0
    proj_kernel<FF><<<pgrid, 256, PROJ_SMEM>>>(x, W_ih0, b_ih0, b_hh0, xp);
    lstm_kernel<<<128, 512, LSTM_SMEM>>>(xp, W_hh0, h0, nullptr, 1);

    // Layer 1
    proj_kernel<HH><<<pgrid, 256, PROJ_SMEM>>>(h0, W_ih1, b_ih1, b_hh1, xp);
    lstm_kernel<<<128, 512, LSTM_SMEM>>>(xp, W_hh1, nullptr, h1, 0);

    // FC head
    fc_kernel<<<BB, 64>>>(h1, fc_w, fc_b, out);
}

// round 15
// speedup vs baseline: 1.5241x; 1.0097x over previous
#include <cuda_runtime.h>
#include <cstdint>

typedef unsigned long long u64;

#define BB 512
#define SS 512
#define FF 64
#define HH 128
#define GG 512   // 4*H
#define OO 64

// ---- scratch (static __device__ globals: allocation-free rule) ----
__device__ float g_xp[(size_t)BB * SS * GG];   // 512 MB, reused across layers
__device__ float g_h0[(size_t)BB * SS * HH];   // 64 MB  (layer0 hidden sequence)
__device__ float g_h1[BB * HH];                // layer1 last hidden

// ---- packed f32x2 helpers (sm_103a FFMA2 path) ----
__device__ __forceinline__ u64 ffma2(u64 a, u64 b, u64 c) {
    u64 d; asm("fma.rn.f32x2 %0,%1,%2,%3;" : "=l"(d) : "l"(a), "l"(b), "l"(c)); return d;
}
__device__ __forceinline__ u64 pack2(float x) {
    u64 d; asm("mov.b64 %0,{%1,%1};" : "=l"(d) : "f"(x)); return d;
}
__device__ __forceinline__ float2 unpack2(u64 v) {
    float2 r; asm("mov.b64 {%0,%1},%2;" : "=f"(r.x), "=f"(r.y) : "l"(v)); return r;
}

// ---- fast activations via MUFU.TANH (single instruction on sm_103a) ----
__device__ __forceinline__ float tanh_ap(float x) {
    float y; asm("tanh.approx.f32 %0, %1;" : "=f"(y) : "f"(x)); return y;
}
__device__ __forceinline__ float sig_ap(float x) {
    // sigmoid(x) = 0.5*tanh(x/2) + 0.5
    return fmaf(0.5f, tanh_ap(0.5f * x), 0.5f);
}

// =====================================================================
// Projection GEMM (FFMA2, double-buffered 16-k chunks, 2 CTAs/SM):
// out[M,512] = A[M,K] @ W[512,K]^T + ba + bb
// 1D grid, n-fast: 4 consecutive CTAs share one A tile (L2 reuse).
// block = 256 (thread = 8m x 8n). Bias LDGs hoisted before main loop.
// =====================================================================
#define KPAD 136
#define TBUF (16 * KPAD)   // 2176 floats per buffer

template <int K>
__global__ __launch_bounds__(256, 2) void proj_kernel(
    const float* __restrict__ A, const float* __restrict__ W,
    const float* __restrict__ ba, const float* __restrict__ bb,
    float* __restrict__ out)
{
    extern __shared__ float sm[];
    float* smA = sm;               // 2 x TBUF
    float* smW = sm + 2 * TBUF;    // 2 x TBUF

    const int tid = threadIdx.x;
    const int m0 = (blockIdx.x >> 2) * 128;
    const int n0 = (blockIdx.x & 3) * 128;
    const int NC = K / 16;

    const int rl = tid >> 2;       // load row 0..63
    const int k4 = tid & 3;        // k-quad within chunk

    const int mb = (tid >> 4) * 8;   // m-octet
    const int nb = (tid & 15) * 8;   // n-octet

    float bias[8];
    #pragma unroll
    for (int j = 0; j < 8; j++)
        bias[j] = ba[n0 + nb + j] + bb[n0 + nb + j];

    {
        float4 a0 = *(const float4*)(A + (size_t)(m0 + rl) * K + k4 * 4);
        float4 a1 = *(const float4*)(A + (size_t)(m0 + rl + 64) * K + k4 * 4);
        float4 w0 = *(const float4*)(W + (size_t)(n0 + rl) * K + k4 * 4);
        float4 w1 = *(const float4*)(W + (size_t)(n0 + rl + 64) * K + k4 * 4);
        #pragma unroll
        for (int j = 0; j < 4; j++) {
            float av0 = (j==0)?a0.x:(j==1)?a0.y:(j==2)?a0.z:a0.w;
            float av1 = (j==0)?a1.x:(j==1)?a1.y:(j==2)?a1.z:a1.w;
            float wv0 = (j==0)?w0.x:(j==1)?w0.y:(j==2)?w0.z:w0.w;
            float wv1 = (j==0)?w1.x:(j==1)?w1.y:(j==2)?w1.z:w1.w;
            smA[(k4*4+j)*KPAD + rl]      = av0;
            smA[(k4*4+j)*KPAD + rl + 64] = av1;
            smW[(k4*4+j)*KPAD + rl]      = wv0;
            smW[(k4*4+j)*KPAD + rl + 64] = wv1;
        }
    }
    __syncthreads();

    u64 acc[4][8];
    #pragma unroll
    for (int p = 0; p < 4; p++)
        #pragma unroll
        for (int j = 0; j < 8; j++) acc[p][j] = 0ull;

    int buf = 0;
    for (int c = 0; c < NC; c++) {
        float4 pa0, pa1, pw0, pw1;
        const bool pf = (c + 1 < NC);
        if (pf) {
            const int k0 = (c + 1) * 16;
            pa0 = *(const float4*)(A + (size_t)(m0 + rl) * K + k0 + k4 * 4);
            pa1 = *(const float4*)(A + (size_t)(m0 + rl + 64) * K + k0 + k4 * 4);
            pw0 = *(const float4*)(W + (size_t)(n0 + rl) * K + k0 + k4 * 4);
            pw1 = *(const float4*)(W + (size_t)(n0 + rl + 64) * K + k0 + k4 * 4);
        }

        const float* bA = smA + buf * TBUF;
        const float* bW = smW + buf * TBUF;
        #pragma unroll
        for (int kk = 0; kk < 16; kk++) {
            ulonglong2 aA = *(const ulonglong2*)(bA + kk * KPAD + mb);
            ulonglong2 aB = *(const ulonglong2*)(bA + kk * KPAD + mb + 4);
            float4 w0 = *(const float4*)(bW + kk * KPAD + nb);
            float4 w1 = *(const float4*)(bW + kk * KPAD + nb + 4);
            u64 ap[4] = {aA.x, aA.y, aB.x, aB.y};
            float wf[8] = {w0.x, w0.y, w0.z, w0.w, w1.x, w1.y, w1.z, w1.w};
            #pragma unroll
            for (int j = 0; j < 8; j++) {
                u64 wp = pack2(wf[j]);
                #pragma unroll
                for (int p = 0; p < 4; p++)
                    acc[p][j] = ffma2(ap[p], wp, acc[p][j]);
            }
        }

        if (pf) {
            float* dA = smA + (buf ^ 1) * TBUF;
            float* dW = smW + (buf ^ 1) * TBUF;
            #pragma unroll
            for (int j = 0; j < 4; j++) {
                float av0 = (j==0)?pa0.x:(j==1)?pa0.y:(j==2)?pa0.z:pa0.w;
                float av1 = (j==0)?pa1.x:(j==1)?pa1.y:(j==2)?pa1.z:pa1.w;
                float wv0 = (j==0)?pw0.x:(j==1)?pw0.y:(j==2)?pw0.z:pw0.w;
                float wv1 = (j==0)?pw1.x:(j==1)?pw1.y:(j==2)?pw1.z:pw1.w;
                dA[(k4*4+j)*KPAD + rl]      = av0;
                dA[(k4*4+j)*KPAD + rl + 64] = av1;
                dW[(k4*4+j)*KPAD + rl]      = wv0;
                dW[(k4*4+j)*KPAD + rl + 64] = wv1;
            }
        }
        __syncthreads();
        buf ^= 1;
    }

    #pragma unroll
    for (int p = 0; p < 4; p++) {
        float r0[8], r1[8];
        #pragma unroll
        for (int j = 0; j < 8; j++) {
            float2 v = unpack2(acc[p][j]);
            r0[j] = v.x + bias[j];
            r1[j] = v.y + bias[j];
        }
        float* o0 = out + (size_t)(m0 + mb + 2 * p) * GG + n0 + nb;
        float* o1 = o0 + GG;
        *(float4*)(o0)     = make_float4(r0[0], r0[1], r0[2], r0[3]);
        *(float4*)(o0 + 4) = make_float4(r0[4], r0[5], r0[6], r0[7]);
        *(float4*)(o1)     = make_float4(r1[0], r1[1], r1[2], r1[3]);
        *(float4*)(o1 + 4) = make_float4(r1[4], r1[5], r1[6], r1[7]);
    }
}

// =====================================================================
// Recurrent LSTM layer (R9 structure + MUFU.TANH activations).
// split-k GEMM around the cluster barrier; cluster = 2 CTAs, 8 batch
// rows; CTA owns 64 hidden cols (256 gate rows). Thread = 2 rows x
// (16 own k + 16 peer k), 64 W regs. gsm coalesced. 128 CTAs x 512.
// =====================================================================
__global__ void __cluster_dims__(2, 1, 1) __launch_bounds__(512, 1) lstm_kernel(
    const float* __restrict__ xp,    // [B, S, 4H]
    const float* __restrict__ W_hh,  // [4H, H]
    float* __restrict__ hseq,        // [B, S, H]  (layer 0)
    float* __restrict__ hlast,       // [B, H]     (layer 1)
    int store_seq)
{
    extern __shared__ float sm[];
    float* hsm = sm;          // 2 x [2 grp][128 k][4 b] = 2 x 1024
    float* gsm = sm + 2048;   // [4 kq][8 b][256 row] = 8192

    const int tid    = threadIdx.x;
    const int rank   = blockIdx.x & 1;
    const int peer   = rank ^ 1;
    const int batch0 = (blockIdx.x >> 1) * 8;

    const int kq = tid >> 7;         // k-segment 0..3 (16 k within each half)
    const int rr = tid & 127;        // local row-pair id
    const int grow0 = (rr >> 6) * 128 + rank * 64 + (rr & 63);
    const int grow1 = grow0 + 256;

    const int ok = rank * 64 + kq * 16;   // own-half k base
    const int pk = peer * 64 + kq * 16;   // peer-half k base

    // ---- W into registers: [0..15] own-half k, [16..31] peer-half k
    float w0[32], w1[32];
    {
        const float4* q;
        q = (const float4*)(W_hh + (size_t)grow0 * HH + ok);
        #pragma unroll
        for (int j = 0; j < 4; j++) {
            float4 v = q[j];
            w0[4*j+0]=v.x; w0[4*j+1]=v.y; w0[4*j+2]=v.z; w0[4*j+3]=v.w;
        }
        q = (const float4*)(W_hh + (size_t)grow0 * HH + pk);
        #pragma unroll
        for (int j = 0; j < 4; j++) {
            float4 v = q[j];
            w0[16+4*j+0]=v.x; w0[16+4*j+1]=v.y; w0[16+4*j+2]=v.z; w0[16+4*j+3]=v.w;
        }
        q = (const float4*)(W_hh + (size_t)grow1 * HH + ok);
        #pragma unroll
        for (int j = 0; j < 4; j++) {
            float4 v = q[j];
            w1[4*j+0]=v.x; w1[4*j+1]=v.y; w1[4*j+2]=v.z; w1[4*j+3]=v.w;
        }
        q = (const float4*)(W_hh + (size_t)grow1 * HH + pk);
        #pragma unroll
        for (int j = 0; j < 4; j++) {
            float4 v = q[j];
            w1[16+4*j+0]=v.x; w1[16+4*j+1]=v.y; w1[16+4*j+2]=v.z; w1[16+4*j+3]=v.w;
        }
    }
    for (int i = tid; i < 2048; i += 512) hsm[i] = 0.0f;

    // init sync; then pre-arm for the first in-loop wait
    asm volatile("barrier.cluster.arrive.aligned;\n" ::: "memory");
    asm volatile("barrier.cluster.wait.aligned;\n" ::: "memory");
    asm volatile("barrier.cluster.arrive.aligned;\n" ::: "memory");

    // update mapping: one (col, batch) per thread
    const int ub  = tid >> 6;        // batch 0..7
    const int ucl = tid & 63;        // local col
    const int col = rank * 64 + ucl;

    float creg = 0.0f;
    int buf = 0;

    for (int s = 0; s < SS; s++) {
        const float* Hb = hsm + buf * 1024;
        float* Hn = hsm + (buf ^ 1) * 1024;

        // xp prefetch (consumed in update; overlaps both GEMM halves)
        float xv0, xv1, xv2, xv3;
        {
            const float* xpp = xp + ((size_t)(batch0 + ub) * SS + s) * GG + rank * 64 + ucl;
            xv0 = xpp[0];
            xv1 = xpp[128];
            xv2 = xpp[256];
            xv3 = xpp[384];
        }

        u64 a00 = 0, a01 = 0, a02 = 0, a03 = 0;
        u64 a10 = 0, a11 = 0, a12 = 0, a13 = 0;

        // ---- GEMM half 1: own-half k (locally produced, no barrier needed)
        #pragma unroll
        for (int kk = 0; kk < 16; kk++) {
            ulonglong2 hA = *(const ulonglong2*)(Hb + (ok + kk) * 4);        // b0..b3
            ulonglong2 hB = *(const ulonglong2*)(Hb + 512 + (ok + kk) * 4);  // b4..b7
            u64 wp0 = pack2(w0[kk]);
            u64 wp1 = pack2(w1[kk]);
            a00 = ffma2(hA.x, wp0, a00);
            a01 = ffma2(hA.y, wp0, a01);
            a02 = ffma2(hB.x, wp0, a02);
            a03 = ffma2(hB.y, wp0, a03);
            a10 = ffma2(hA.x, wp1, a10);
            a11 = ffma2(hA.y, wp1, a11);
            a12 = ffma2(hB.x, wp1, a12);
            a13 = ffma2(hB.y, wp1, a13);
        }

        // wait for peer's h half (latency hidden behind GEMM half 1)
        asm volatile("barrier.cluster.wait.aligned;\n" ::: "memory");

        // ---- GEMM half 2: peer-half k
        #pragma unroll
        for (int kk = 0; kk < 16; kk++) {
            ulonglong2 hA = *(const ulonglong2*)(Hb + (pk + kk) * 4);
            ulonglong2 hB = *(const ulonglong2*)(Hb + 512 + (pk + kk) * 4);
            u64 wp0 = pack2(w0[16 + kk]);
            u64 wp1 = pack2(w1[16 + kk]);
            a00 = ffma2(hA.x, wp0, a00);
            a01 = ffma2(hA.y, wp0, a01);
            a02 = ffma2(hB.x, wp0, a02);
            a03 = ffma2(hB.y, wp0, a03);
            a10 = ffma2(hA.x, wp1, a10);
            a11 = ffma2(hA.y, wp1, a11);
            a12 = ffma2(hB.x, wp1, a12);
            a13 = ffma2(hB.y, wp1, a13);
        }

        // write partials COALESCED: gsm[kq][b][row]
        {
            float* g0 = gsm + kq * 2048 + rr;          // row rr
            float* g1 = g0 + 128;                      // row rr+128
            float2 v;
            v = unpack2(a00); g0[0 * 256] = v.x; g0[1 * 256] = v.y;
            v = unpack2(a01); g0[2 * 256] = v.x; g0[3 * 256] = v.y;
            v = unpack2(a02); g0[4 * 256] = v.x; g0[5 * 256] = v.y;
            v = unpack2(a03); g0[6 * 256] = v.x; g0[7 * 256] = v.y;
            v = unpack2(a10); g1[0 * 256] = v.x; g1[1 * 256] = v.y;
            v = unpack2(a11); g1[2 * 256] = v.x; g1[3 * 256] = v.y;
            v = unpack2(a12); g1[4 * 256] = v.x; g1[5 * 256] = v.y;
            v = unpack2(a13); g1[6 * 256] = v.x; g1[7 * 256] = v.y;
        }
        __syncthreads();

        // ---- nonlinearity + state update: thread -> (col, batch ub)
        float hh;
        {
            float g4[4] = {xv0, xv1, xv2, xv3};
            #pragma unroll
            for (int gt = 0; gt < 4; gt++) {
                const int base = ub * 256 + gt * 64 + ucl;
                g4[gt] += gsm[base];
                g4[gt] += gsm[2048 + base];
                g4[gt] += gsm[4096 + base];
                g4[gt] += gsm[6144 + base];
            }
            float iv = sig_ap(g4[0]);
            float fv = sig_ap(g4[1]);
            float gv = tanh_ap(g4[2]);
            float ov = sig_ap(g4[3]);
            creg = fmaf(fv, creg, iv * gv);
            hh = ov * tanh_ap(creg);

            const int hoff = (ub >> 2) * 512 + col * 4 + (ub & 3);
            Hn[hoff] = hh;
            uint32_t la = (uint32_t)__cvta_generic_to_shared(Hn + hoff);
            uint32_t ra;
            asm("mapa.shared::cluster.u32 %0, %1, %2;" : "=r"(ra) : "r"(la), "r"(peer));
            asm volatile("st.shared::cluster.f32 [%0], %1;" :: "r"(ra), "f"(hh) : "memory");
        }

        // arrive (release: orders the remote h store); global store after
        asm volatile("barrier.cluster.arrive.aligned;\n" ::: "memory");

        if (store_seq) {
            hseq[((size_t)(batch0 + ub) * SS + s) * HH + col] = hh;
        } else if (s == SS - 1) {
            hlast[(batch0 + ub) * HH + col] = hh;
        }

        // order local Hn writes before next step's GEMM half 1 reads
        __syncthreads();
        buf ^= 1;
    }

    // drain the final arrive (keeps smem alive for peer's last store)
    asm volatile("barrier.cluster.wait.aligned;\n" ::: "memory");
}

// =====================================================================
// Final FC: out[b,o] = relu(h1[b,:]) @ fc_w[o,:] + fc_b[o]
// =====================================================================
__global__ __launch_bounds__(64) void fc_kernel(
    const float* __restrict__ h1, const float* __restrict__ fcw,
    const float* __restrict__ fcb, float* __restrict__ out)
{
    __shared__ float hs[HH];
    const int b = blockIdx.x;
    const int o = threadIdx.x;
    hs[o]      = fmaxf(h1[b * HH + o], 0.0f);
    hs[o + 64] = fmaxf(h1[b * HH + o + 64], 0.0f);
    __syncthreads();
    float acc = fcb[o];
    const float* wr = fcw + o * HH;
    #pragma unroll 8
    for (int k = 0; k < HH; k++)
        acc = fmaf(hs[k], wr[k], acc);
    out[b * OO + o] = acc;
}

// =====================================================================
extern "C" void kernel_launch(void* const* d_in, const int* in_sizes, int n_in,
                              void* d_out, int out_size)
{
    (void)in_sizes; (void)n_in; (void)out_size;
    const float* x     = (const float*)d_in[0];
    const float* W_ih0 = (const float*)d_in[1];
    const float* W_hh0 = (const float*)d_in[2];
    const float* b_ih0 = (const float*)d_in[3];
    const float* b_hh0 = (const float*)d_in[4];
    const float* W_ih1 = (const float*)d_in[5];
    const float* W_hh1 = (const float*)d_in[6];
    const float* b_ih1 = (const float*)d_in[7];
    const float* b_hh1 = (const float*)d_in[8];
    const float* fc_w  = (const float*)d_in[9];
    const float* fc_b  = (const float*)d_in[10];
    float* out = (float*)d_out;

    float *xp, *h0, *h1;
    cudaGetSymbolAddress((void**)&xp, g_xp);
    cudaGetSymbolAddress((void**)&h0, g_h0);
    cudaGetSymbolAddress((void**)&h1, g_h1);

    const int PROJ_SMEM = 4 * TBUF * 4;             // 34816
    const int LSTM_SMEM = (2048 + 8192) * 4;        // 40960

    cudaFuncSetAttribute(proj_kernel<FF>, cudaFuncAttributeMaxDynamicSharedMemorySize, PROJ_SMEM);
    cudaFuncSetAttribute(proj_kernel<HH>, cudaFuncAttributeMaxDynamicSharedMemorySize, PROJ_SMEM);
    cudaFuncSetAttribute(lstm_kernel, cudaFuncAttributeMaxDynamicSharedMemorySize, LSTM_SMEM);

    const int pgrid = ((BB * SS) / 128) * (GG / 128);   // 8192, n-fast

    // Layer 0
    proj_kernel<FF><<<pgrid, 256, PROJ_SMEM>>>(x, W_ih0, b_ih0, b_hh0, xp);
    lstm_kernel<<<128, 512, LSTM_SMEM>>>(xp, W_hh0, h0, nullptr, 1);

    // Layer 1
    proj_kernel<HH><<<pgrid, 256, PROJ_SMEM>>>(h0, W_ih1, b_ih1, b_hh1, xp);
    lstm_kernel<<<128, 512, LSTM_SMEM>>>(xp, W_hh1, nullptr, h1, 0);

    // FC head
    fc_kernel<<<BB, 64>>>(h1, fc_w, fc_b, out);
}

// round 16
// speedup vs baseline: 1.6842x; 1.1051x over previous
#include <cuda_runtime.h>
#include <cstdint>

typedef unsigned long long u64;

#define BB 512
#define SS 512
#define FF 64
#define HH 128
#define GG 512   // 4*H
#define OO 64

// ---- scratch (static __device__ globals: allocation-free rule) ----
__device__ float g_xp[(size_t)BB * SS * GG];   // 512 MB, reused across layers
__device__ float g_h0[(size_t)BB * SS * HH];   // 64 MB  (layer0 hidden sequence)
__device__ float g_h1[BB * HH];                // layer1 last hidden

// ---- packed f32x2 helpers (sm_103a FFMA2 path) ----
__device__ __forceinline__ u64 ffma2(u64 a, u64 b, u64 c) {
    u64 d; asm("fma.rn.f32x2 %0,%1,%2,%3;" : "=l"(d) : "l"(a), "l"(b), "l"(c)); return d;
}
__device__ __forceinline__ u64 pack2(float x) {
    u64 d; asm("mov.b64 %0,{%1,%1};" : "=l"(d) : "f"(x)); return d;
}
__device__ __forceinline__ float2 unpack2(u64 v) {
    float2 r; asm("mov.b64 {%0,%1},%2;" : "=f"(r.x), "=f"(r.y) : "l"(v)); return r;
}

// ---- fast activations via MUFU.TANH ----
__device__ __forceinline__ float tanh_ap(float x) {
    float y; asm("tanh.approx.f32 %0, %1;" : "=f"(y) : "f"(x)); return y;
}
__device__ __forceinline__ float sig_ap(float x) {
    return fmaf(0.5f, tanh_ap(0.5f * x), 0.5f);
}

__device__ __forceinline__ uint32_t smem_u32(const void* p) {
    uint32_t a;
    asm("{ .reg .u64 t; cvta.to.shared.u64 t, %1; cvt.u32.u64 %0, t; }" : "=r"(a) : "l"(p));
    return a;
}

// ---- mbarrier helpers ----
#define MBAR_INIT(a, n) \
    asm volatile("mbarrier.init.shared.b64 [%0], %1;" :: "r"((uint32_t)(a)), "r"((uint32_t)(n)) : "memory")
#define MBAR_ARRIVE_EXPECT_TX(a, n) \
    asm volatile("mbarrier.arrive.expect_tx.shared.b64 _, [%0], %1;" :: "r"((uint32_t)(a)), "r"((uint32_t)(n)) : "memory")
#define MBAR_TRYWAIT(a, ph) do { \
    asm volatile("{\n\t.reg .pred P;\n\tW1_%=:\n\t" \
        "mbarrier.try_wait.parity.acquire.cluster.shared::cta.b64 P, [%0], %1, 0x989680;\n\t" \
        "@P bra.uni W2_%=;\n\tbra.uni W1_%=;\n\tW2_%=:\n\t}" \
        :: "r"((uint32_t)(a)), "r"((uint32_t)(ph)) : "memory"); \
} while (0)
#define ST_ASYNC_F32(ra, v, rm) \
    asm volatile("st.async.shared::cluster.mbarrier::complete_tx::bytes.u32 [%0], %1, [%2];" \
                 :: "r"(ra), "r"(v), "r"(rm) : "memory")

// =====================================================================
// Projection GEMM (FFMA2, double-buffered 16-k chunks, 2 CTAs/SM):
// out[M,512] = A[M,K] @ W[512,K]^T + ba + bb
// 1D grid, n-fast. block = 256 (thread = 8m x 8n). Bias hoisted.
// =====================================================================
#define KPAD 136
#define TBUF (16 * KPAD)   // 2176 floats per buffer

template <int K>
__global__ __launch_bounds__(256, 2) void proj_kernel(
    const float* __restrict__ A, const float* __restrict__ W,
    const float* __restrict__ ba, const float* __restrict__ bb,
    float* __restrict__ out)
{
    extern __shared__ float sm[];
    float* smA = sm;               // 2 x TBUF
    float* smW = sm + 2 * TBUF;    // 2 x TBUF

    const int tid = threadIdx.x;
    const int m0 = (blockIdx.x >> 2) * 128;
    const int n0 = (blockIdx.x & 3) * 128;
    const int NC = K / 16;

    const int rl = tid >> 2;       // load row 0..63
    const int k4 = tid & 3;        // k-quad within chunk

    const int mb = (tid >> 4) * 8;   // m-octet
    const int nb = (tid & 15) * 8;   // n-octet

    float bias[8];
    #pragma unroll
    for (int j = 0; j < 8; j++)
        bias[j] = ba[n0 + nb + j] + bb[n0 + nb + j];

    {
        float4 a0 = *(const float4*)(A + (size_t)(m0 + rl) * K + k4 * 4);
        float4 a1 = *(const float4*)(A + (size_t)(m0 + rl + 64) * K + k4 * 4);
        float4 w0 = *(const float4*)(W + (size_t)(n0 + rl) * K + k4 * 4);
        float4 w1 = *(const float4*)(W + (size_t)(n0 + rl + 64) * K + k4 * 4);
        #pragma unroll
        for (int j = 0; j < 4; j++) {
            float av0 = (j==0)?a0.x:(j==1)?a0.y:(j==2)?a0.z:a0.w;
            float av1 = (j==0)?a1.x:(j==1)?a1.y:(j==2)?a1.z:a1.w;
            float wv0 = (j==0)?w0.x:(j==1)?w0.y:(j==2)?w0.z:w0.w;
            float wv1 = (j==0)?w1.x:(j==1)?w1.y:(j==2)?w1.z:w1.w;
            smA[(k4*4+j)*KPAD + rl]      = av0;
            smA[(k4*4+j)*KPAD + rl + 64] = av1;
            smW[(k4*4+j)*KPAD + rl]      = wv0;
            smW[(k4*4+j)*KPAD + rl + 64] = wv1;
        }
    }
    __syncthreads();

    u64 acc[4][8];
    #pragma unroll
    for (int p = 0; p < 4; p++)
        #pragma unroll
        for (int j = 0; j < 8; j++) acc[p][j] = 0ull;

    int buf = 0;
    for (int c = 0; c < NC; c++) {
        float4 pa0, pa1, pw0, pw1;
        const bool pf = (c + 1 < NC);
        if (pf) {
            const int k0 = (c + 1) * 16;
            pa0 = *(const float4*)(A + (size_t)(m0 + rl) * K + k0 + k4 * 4);
            pa1 = *(const float4*)(A + (size_t)(m0 + rl + 64) * K + k0 + k4 * 4);
            pw0 = *(const float4*)(W + (size_t)(n0 + rl) * K + k0 + k4 * 4);
            pw1 = *(const float4*)(W + (size_t)(n0 + rl + 64) * K + k0 + k4 * 4);
        }

        const float* bA = smA + buf * TBUF;
        const float* bW = smW + buf * TBUF;
        #pragma unroll
        for (int kk = 0; kk < 16; kk++) {
            ulonglong2 aA = *(const ulonglong2*)(bA + kk * KPAD + mb);
            ulonglong2 aB = *(const ulonglong2*)(bA + kk * KPAD + mb + 4);
            float4 w0 = *(const float4*)(bW + kk * KPAD + nb);
            float4 w1 = *(const float4*)(bW + kk * KPAD + nb + 4);
            u64 ap[4] = {aA.x, aA.y, aB.x, aB.y};
            float wf[8] = {w0.x, w0.y, w0.z, w0.w, w1.x, w1.y, w1.z, w1.w};
            #pragma unroll
            for (int j = 0; j < 8; j++) {
                u64 wp = pack2(wf[j]);
                #pragma unroll
                for (int p = 0; p < 4; p++)
                    acc[p][j] = ffma2(ap[p], wp, acc[p][j]);
            }
        }

        if (pf) {
            float* dA = smA + (buf ^ 1) * TBUF;
            float* dW = smW + (buf ^ 1) * TBUF;
            #pragma unroll
            for (int j = 0; j < 4; j++) {
                float av0 = (j==0)?pa0.x:(j==1)?pa0.y:(j==2)?pa0.z:pa0.w;
                float av1 = (j==0)?pa1.x:(j==1)?pa1.y:(j==2)?pa1.z:pa1.w;
                float wv0 = (j==0)?pw0.x:(j==1)?pw0.y:(j==2)?pw0.z:pw0.w;
                float wv1 = (j==0)?pw1.x:(j==1)?pw1.y:(j==2)?pw1.z:pw1.w;
                dA[(k4*4+j)*KPAD + rl]      = av0;
                dA[(k4*4+j)*KPAD + rl + 64] = av1;
                dW[(k4*4+j)*KPAD + rl]      = wv0;
                dW[(k4*4+j)*KPAD + rl + 64] = wv1;
            }
        }
        __syncthreads();
        buf ^= 1;
    }

    #pragma unroll
    for (int p = 0; p < 4; p++) {
        float r0[8], r1[8];
        #pragma unroll
        for (int j = 0; j < 8; j++) {
            float2 v = unpack2(acc[p][j]);
            r0[j] = v.x + bias[j];
            r1[j] = v.y + bias[j];
        }
        float* o0 = out + (size_t)(m0 + mb + 2 * p) * GG + n0 + nb;
        float* o1 = o0 + GG;
        *(float4*)(o0)     = make_float4(r0[0], r0[1], r0[2], r0[3]);
        *(float4*)(o0 + 4) = make_float4(r0[4], r0[5], r0[6], r0[7]);
        *(float4*)(o1)     = make_float4(r1[0], r1[1], r1[2], r1[3]);
        *(float4*)(o1 + 4) = make_float4(r1[4], r1[5], r1[6], r1[7]);
    }
}

// =====================================================================
// Recurrent LSTM layer — mbarrier tx-handshake replaces the per-step
// cluster barrier. split-k GEMM around the try_wait; cluster = 2 CTAs,
// 8 batch rows; CTA owns 64 hidden cols. Thread = 2 rows x (16 own k +
// 16 peer k), 64 W regs. Peer h delivered via st.async (2048B/step).
// grid = 128 CTAs, block = 512.
// =====================================================================
__global__ void __cluster_dims__(2, 1, 1) __launch_bounds__(512, 1) lstm_kernel(
    const float* __restrict__ xp,    // [B, S, 4H]
    const float* __restrict__ W_hh,  // [4H, H]
    float* __restrict__ hseq,        // [B, S, H]  (layer 0)
    float* __restrict__ hlast,       // [B, H]     (layer 1)
    int store_seq)
{
    extern __shared__ float sm[];
    float* hsm = sm;          // 2 x [2 grp][128 k][4 b] = 2 x 1024
    float* gsm = sm + 2048;   // [4 kq][8 b][256 row] = 8192
    // mbarriers at float offset 10240 (byte 40960): mbar[0], mbar[1]

    const int tid    = threadIdx.x;
    const int rank   = blockIdx.x & 1;
    const int peer   = rank ^ 1;
    const int batch0 = (blockIdx.x >> 1) * 8;

    const uint32_t mbar_base = smem_u32(sm) + 40960;

    const int kq = tid >> 7;         // k-segment 0..3 (16 k within each half)
    const int rr = tid & 127;        // local row-pair id
    const int grow0 = (rr >> 6) * 128 + rank * 64 + (rr & 63);
    const int grow1 = grow0 + 256;

    const int ok = rank * 64 + kq * 16;   // own-half k base
    const int pk = peer * 64 + kq * 16;   // peer-half k base

    // ---- W into registers: [0..15] own-half k, [16..31] peer-half k
    float w0[32], w1[32];
    {
        const float4* q;
        q = (const float4*)(W_hh + (size_t)grow0 * HH + ok);
        #pragma unroll
        for (int j = 0; j < 4; j++) {
            float4 v = q[j];
            w0[4*j+0]=v.x; w0[4*j+1]=v.y; w0[4*j+2]=v.z; w0[4*j+3]=v.w;
        }
        q = (const float4*)(W_hh + (size_t)grow0 * HH + pk);
        #pragma unroll
        for (int j = 0; j < 4; j++) {
            float4 v = q[j];
            w0[16+4*j+0]=v.x; w0[16+4*j+1]=v.y; w0[16+4*j+2]=v.z; w0[16+4*j+3]=v.w;
        }
        q = (const float4*)(W_hh + (size_t)grow1 * HH + ok);
        #pragma unroll
        for (int j = 0; j < 4; j++) {
            float4 v = q[j];
            w1[4*j+0]=v.x; w1[4*j+1]=v.y; w1[4*j+2]=v.z; w1[4*j+3]=v.w;
        }
        q = (const float4*)(W_hh + (size_t)grow1 * HH + pk);
        #pragma unroll
        for (int j = 0; j < 4; j++) {
            float4 v = q[j];
            w1[16+4*j+0]=v.x; w1[16+4*j+1]=v.y; w1[16+4*j+2]=v.z; w1[16+4*j+3]=v.w;
        }
    }
    for (int i = tid; i < 2048; i += 512) hsm[i] = 0.0f;

    // init mbars + pre-arm BOTH (before peers can possibly store)
    if (tid == 0) {
        MBAR_INIT(mbar_base + 0, 1);
        MBAR_INIT(mbar_base + 8, 1);
        MBAR_ARRIVE_EXPECT_TX(mbar_base + 0, 2048);
        MBAR_ARRIVE_EXPECT_TX(mbar_base + 8, 2048);
    }
    __syncthreads();
    // cluster barrier: peers' mbar init + hsm zero visible before any st.async
    asm volatile("barrier.cluster.arrive.aligned;\n" ::: "memory");
    asm volatile("barrier.cluster.wait.aligned;\n" ::: "memory");

    // update mapping: one (col, batch) per thread
    const int ub  = tid >> 6;        // batch 0..7
    const int ucl = tid & 63;        // local col
    const int col = rank * 64 + ucl;

    float creg = 0.0f;
    int buf = 0;
    int ph0 = 0, ph1 = 0;

    for (int s = 0; s < SS; s++) {
        const float* Hb = hsm + buf * 1024;
        float* Hn = hsm + (buf ^ 1) * 1024;

        // xp prefetch (overlaps both GEMM halves)
        float xv0, xv1, xv2, xv3;
        {
            const float* xpp = xp + ((size_t)(batch0 + ub) * SS + s) * GG + rank * 64 + ucl;
            xv0 = xpp[0];
            xv1 = xpp[128];
            xv2 = xpp[256];
            xv3 = xpp[384];
        }

        u64 a00 = 0, a01 = 0, a02 = 0, a03 = 0;
        u64 a10 = 0, a11 = 0, a12 = 0, a13 = 0;

        // ---- GEMM half 1: own-half k (locally produced; ordered by the
        //      trailing __syncthreads of the previous step)
        #pragma unroll
        for (int kk = 0; kk < 16; kk++) {
            ulonglong2 hA = *(const ulonglong2*)(Hb + (ok + kk) * 4);        // b0..b3
            ulonglong2 hB = *(const ulonglong2*)(Hb + 512 + (ok + kk) * 4);  // b4..b7
            u64 wp0 = pack2(w0[kk]);
            u64 wp1 = pack2(w1[kk]);
            a00 = ffma2(hA.x, wp0, a00);
            a01 = ffma2(hA.y, wp0, a01);
            a02 = ffma2(hB.x, wp0, a02);
            a03 = ffma2(hB.y, wp0, a03);
            a10 = ffma2(hA.x, wp1, a10);
            a11 = ffma2(hA.y, wp1, a11);
            a12 = ffma2(hB.x, wp1, a12);
            a13 = ffma2(hB.y, wp1, a13);
        }

        // wait for peer's h half (mbarrier tx handshake; ~100 cyc, hidden)
        if (s > 0) {
            const uint32_t mb = mbar_base + buf * 8;
            MBAR_TRYWAIT(mb, (buf ? ph1 : ph0));
            if (tid == 0) MBAR_ARRIVE_EXPECT_TX(mb, 2048);   // re-arm for use at s+2
            if (buf) ph1 ^= 1; else ph0 ^= 1;
        }

        // ---- GEMM half 2: peer-half k
        #pragma unroll
        for (int kk = 0; kk < 16; kk++) {
            ulonglong2 hA = *(const ulonglong2*)(Hb + (pk + kk) * 4);
            ulonglong2 hB = *(const ulonglong2*)(Hb + 512 + (pk + kk) * 4);
            u64 wp0 = pack2(w0[16 + kk]);
            u64 wp1 = pack2(w1[16 + kk]);
            a00 = ffma2(hA.x, wp0, a00);
            a01 = ffma2(hA.y, wp0, a01);
            a02 = ffma2(hB.x, wp0, a02);
            a03 = ffma2(hB.y, wp0, a03);
            a10 = ffma2(hA.x, wp1, a10);
            a11 = ffma2(hA.y, wp1, a11);
            a12 = ffma2(hB.x, wp1, a12);
            a13 = ffma2(hB.y, wp1, a13);
        }

        // write partials COALESCED: gsm[kq][b][row]
        {
            float* g0 = gsm + kq * 2048 + rr;          // row rr
            float* g1 = g0 + 128;                      // row rr+128
            float2 v;
            v = unpack2(a00); g0[0 * 256] = v.x; g0[1 * 256] = v.y;
            v = unpack2(a01); g0[2 * 256] = v.x; g0[3 * 256] = v.y;
            v = unpack2(a02); g0[4 * 256] = v.x; g0[5 * 256] = v.y;
            v = unpack2(a03); g0[6 * 256] = v.x; g0[7 * 256] = v.y;
            v = unpack2(a10); g1[0 * 256] = v.x; g1[1 * 256] = v.y;
            v = unpack2(a11); g1[2 * 256] = v.x; g1[3 * 256] = v.y;
            v = unpack2(a12); g1[4 * 256] = v.x; g1[5 * 256] = v.y;
            v = unpack2(a13); g1[6 * 256] = v.x; g1[7 * 256] = v.y;
        }
        __syncthreads();

        // ---- nonlinearity + state update: thread -> (col, batch ub)
        float hh;
        {
            float g4[4] = {xv0, xv1, xv2, xv3};
            #pragma unroll
            for (int gt = 0; gt < 4; gt++) {
                const int base = ub * 256 + gt * 64 + ucl;
                g4[gt] += gsm[base];
                g4[gt] += gsm[2048 + base];
                g4[gt] += gsm[4096 + base];
                g4[gt] += gsm[6144 + base];
            }
            float iv = sig_ap(g4[0]);
            float fv = sig_ap(g4[1]);
            float gv = tanh_ap(g4[2]);
            float ov = sig_ap(g4[3]);
            creg = fmaf(fv, creg, iv * gv);
            hh = ov * tanh_ap(creg);

            const int hoff = (ub >> 2) * 512 + col * 4 + (ub & 3);
            Hn[hoff] = hh;
            // peer copy via st.async tracked by peer's mbar[buf^1]
            uint32_t la = (uint32_t)__cvta_generic_to_shared(Hn + hoff);
            uint32_t lm = mbar_base + (buf ^ 1) * 8;
            uint32_t ra, rm;
            asm("mapa.shared::cluster.u32 %0, %1, %2;" : "=r"(ra) : "r"(la), "r"(peer));
            asm("mapa.shared::cluster.u32 %0, %1, %2;" : "=r"(rm) : "r"(lm), "r"(peer));
            ST_ASYNC_F32(ra, __float_as_uint(hh), rm);
        }

        if (store_seq) {
            hseq[((size_t)(batch0 + ub) * SS + s) * HH + col] = hh;
        } else if (s == SS - 1) {
            hlast[(batch0 + ub) * HH + col] = hh;
        }

        // order local Hn writes before next step's GEMM half 1 reads
        __syncthreads();
        buf ^= 1;
    }

    // drain: consume the final step's incoming stores (mbar[0], armed at
    // s=510), then cluster barrier so no CTA exits with peer stores inflight
    MBAR_TRYWAIT(mbar_base + 0, ph0);
    asm volatile("barrier.cluster.arrive.aligned;\n" ::: "memory");
    asm volatile("barrier.cluster.wait.aligned;\n" ::: "memory");
}

// =====================================================================
// Final FC: out[b,o] = relu(h1[b,:]) @ fc_w[o,:] + fc_b[o]
// =====================================================================
__global__ __launch_bounds__(64) void fc_kernel(
    const float* __restrict__ h1, const float* __restrict__ fcw,
    const float* __restrict__ fcb, float* __restrict__ out)
{
    __shared__ float hs[HH];
    const int b = blockIdx.x;
    const int o = threadIdx.x;
    hs[o]      = fmaxf(h1[b * HH + o], 0.0f);
    hs[o + 64] = fmaxf(h1[b * HH + o + 64], 0.0f);
    __syncthreads();
    float acc = fcb[o];
    const float* wr = fcw + o * HH;
    #pragma unroll 8
    for (int k = 0; k < HH; k++)
        acc = fmaf(hs[k], wr[k], acc);
    out[b * OO + o] = acc;
}

// =====================================================================
extern "C" void kernel_launch(void* const* d_in, const int* in_sizes, int n_in,
                              void* d_out, int out_size)
{
    (void)in_sizes; (void)n_in; (void)out_size;
    const float* x     = (const float*)d_in[0];
    const float* W_ih0 = (const float*)d_in[1];
    const float* W_hh0 = (const float*)d_in[2];
    const float* b_ih0 = (const float*)d_in[3];
    const float* b_hh0 = (const float*)d_in[4];
    const float* W_ih1 = (const float*)d_in[5];
    const float* W_hh1 = (const float*)d_in[6];
    const float* b_ih1 = (const float*)d_in[7];
    const float* b_hh1 = (const float*)d_in[8];
    const float* fc_w  = (const float*)d_in[9];
    const float* fc_b  = (const float*)d_in[10];
    float* out = (float*)d_out;

    float *xp, *h0, *h1;
    cudaGetSymbolAddress((void**)&xp, g_xp);
    cudaGetSymbolAddress((void**)&h0, g_h0);
    cudaGetSymbolAddress((void**)&h1, g_h1);

    const int PROJ_SMEM = 4 * TBUF * 4;                 // 34816
    const int LSTM_SMEM = (2048 + 8192) * 4 + 16;       // 40976 (incl. 2 mbars)

    cudaFuncSetAttribute(proj_kernel<FF>, cudaFuncAttributeMaxDynamicSharedMemorySize, PROJ_SMEM);
    cudaFuncSetAttribute(proj_kernel<HH>, cudaFuncAttributeMaxDynamicSharedMemorySize, PROJ_SMEM);
    cudaFuncSetAttribute(lstm_kernel, cudaFuncAttributeMaxDynamicSharedMemorySize, LSTM_SMEM);

    const int pgrid = ((BB * SS) / 128) * (GG / 128);   // 8192, n-fast

    // Layer 0
    proj_kernel<FF><<<pgrid, 256, PROJ_SMEM>>>(x, W_ih0, b_ih0, b_hh0, xp);
    lstm_kernel<<<128, 512, LSTM_SMEM>>>(xp, W_hh0, h0, nullptr, 1);

    // Layer 1
    proj_kernel<HH><<<pgrid, 256, PROJ_SMEM>>>(h0, W_ih1, b_ih1, b_hh1, xp);
    lstm_kernel<<<128, 512, LSTM_SMEM>>>(xp, W_hh1, nullptr, h1, 0);

    // FC head
    fc_kernel<<<BB, 64>>>(h1, fc_w, fc_b, out);
}